// round 1
// baseline (speedup 1.0000x reference)
#include <cuda_runtime.h>
#include <math.h>

// Problem constants
#define BATCH 4096
#define T 96
#define C 256
#define H 64
#define SCALE 0.0625f   // C^-0.5 = 1/16

#define NTHREADS 512
#define NWARPS 16
#define CT 32            // c-tile width
#define KPAD 65          // padded row stride for k/q/v in smem (conflict-free scalar LDS)

// Shared memory layout (in floats)
static constexpr int KQV_OFF  = 0;                       // k:[96][65], q, v back-to-back
static constexpr int K_OFF    = KQV_OFF;                 // 0
static constexpr int Q_OFF    = K_OFF + T * KPAD;        // 6240
static constexpr int V_OFF    = Q_OFF + T * KPAD;        // 12480
static constexpr int XT_OFF   = V_OFF + T * KPAD;        // 18720  x tile [96][32]
static constexpr int WT_OFF   = XT_OFF + T * CT;         // 21792  w tile [3][32][64]
static constexpr int WROW_OFF = WT_OFF + 3 * CT * H;     // 27936  per-warp prob row [16][96]
static constexpr int SMEM_FLOATS = WROW_OFF + NWARPS * T;// 29472
static constexpr int SMEM_BYTES  = SMEM_FLOATS * 4;      // 117888 B

__global__ __launch_bounds__(NTHREADS, 1)
void head_attn_kernel(const float* __restrict__ x,
                      const float* __restrict__ Wk,
                      const float* __restrict__ Wq,
                      const float* __restrict__ Wv,
                      float* __restrict__ out)
{
    extern __shared__ float smem[];
    float* ks = smem + K_OFF;
    float* qs = smem + Q_OFF;
    float* vs = smem + V_OFF;
    float* xs = smem + XT_OFF;
    float* wt = smem + WT_OFF;

    const int tid  = threadIdx.x;
    const int b    = blockIdx.x;
    const float* xb = x + (size_t)b * T * C;

    // ---------------- Phase 1: projections q,k,v = x @ W ----------------
    // thread owns column h = tid&63, row-group tg = tid>>6 (rows tg + 8*r, r<12)
    const int h  = tid & 63;
    const int tg = tid >> 6;

    float acck[12], accq[12], accv[12];
#pragma unroll
    for (int r = 0; r < 12; r++) { acck[r] = 0.f; accq[r] = 0.f; accv[r] = 0.f; }

    for (int c0 = 0; c0 < C; c0 += CT) {
        // load x tile [96][32] as float2: 1536 float2, 3 per thread
#pragma unroll
        for (int i = 0; i < 3; i++) {
            int idx  = tid + i * NTHREADS;        // 0..1535
            int row  = idx >> 4;                  // 16 float2 per row
            int col2 = idx & 15;
            float2 v2 = *(const float2*)&xb[row * C + c0 + col2 * 2];
            *(float2*)&xs[row * CT + col2 * 2] = v2;
        }
        // load W tile [3][32][64] as float4: 1536 float4, 3 per thread (m == i)
        {
            int rem  = tid;                       // 0..511
            int row  = rem >> 4;                  // 16 float4 per row
            int col4 = rem & 15;
            float4 a = *(const float4*)&Wk[(c0 + row) * H + col4 * 4];
            *(float4*)&wt[0 * 2048 + row * H + col4 * 4] = a;
            float4 bq = *(const float4*)&Wq[(c0 + row) * H + col4 * 4];
            *(float4*)&wt[1 * 2048 + row * H + col4 * 4] = bq;
            float4 cv = *(const float4*)&Wv[(c0 + row) * H + col4 * 4];
            *(float4*)&wt[2 * 2048 + row * H + col4 * 4] = cv;
        }
        __syncthreads();

#pragma unroll 2
        for (int dc = 0; dc < CT; dc += 4) {
            const float wk0 = wt[0 * 2048 + (dc + 0) * H + h];
            const float wk1 = wt[0 * 2048 + (dc + 1) * H + h];
            const float wk2 = wt[0 * 2048 + (dc + 2) * H + h];
            const float wk3 = wt[0 * 2048 + (dc + 3) * H + h];
            const float wq0 = wt[1 * 2048 + (dc + 0) * H + h];
            const float wq1 = wt[1 * 2048 + (dc + 1) * H + h];
            const float wq2 = wt[1 * 2048 + (dc + 2) * H + h];
            const float wq3 = wt[1 * 2048 + (dc + 3) * H + h];
            const float wv0 = wt[2 * 2048 + (dc + 0) * H + h];
            const float wv1 = wt[2 * 2048 + (dc + 1) * H + h];
            const float wv2 = wt[2 * 2048 + (dc + 2) * H + h];
            const float wv3 = wt[2 * 2048 + (dc + 3) * H + h];
#pragma unroll
            for (int r = 0; r < 12; r++) {
                const float4 xv = *(const float4*)&xs[(tg + 8 * r) * CT + dc];
                acck[r] = fmaf(xv.x, wk0, acck[r]);
                accq[r] = fmaf(xv.x, wq0, accq[r]);
                accv[r] = fmaf(xv.x, wv0, accv[r]);
                acck[r] = fmaf(xv.y, wk1, acck[r]);
                accq[r] = fmaf(xv.y, wq1, accq[r]);
                accv[r] = fmaf(xv.y, wv1, accv[r]);
                acck[r] = fmaf(xv.z, wk2, acck[r]);
                accq[r] = fmaf(xv.z, wq2, accq[r]);
                accv[r] = fmaf(xv.z, wv2, accv[r]);
                acck[r] = fmaf(xv.w, wk3, acck[r]);
                accq[r] = fmaf(xv.w, wq3, accq[r]);
                accv[r] = fmaf(xv.w, wv3, accv[r]);
            }
        }
        __syncthreads();   // protect tiles before next iteration overwrites
    }

    // write q,k,v to padded smem
#pragma unroll
    for (int r = 0; r < 12; r++) {
        int t = tg + 8 * r;
        ks[t * KPAD + h] = acck[r];
        qs[t * KPAD + h] = accq[r];
        vs[t * KPAD + h] = accv[r];
    }
    __syncthreads();

    // ---------------- Phase 2: causal softmax attention ----------------
    const int wid  = tid >> 5;
    const int lane = tid & 31;
    float* wrow = smem + WROW_OFF + wid * T;

    for (int j = 0; j < 6; j++) {
        const int t  = wid + NWARPS * j;   // 0..95
        const int ns = t + 1;

        // scores: lane handles s = lane, lane+32, lane+64
        float sc[3];
        float mx = -INFINITY;
        const float* qr = &qs[t * KPAD];
#pragma unroll
        for (int i = 0; i < 3; i++) {
            int s = lane + 32 * i;
            float d = 0.f;
            if (s < ns) {
                const float* kr = &ks[s * KPAD];
#pragma unroll
                for (int hh = 0; hh < H; hh += 4) {
                    d = fmaf(qr[hh + 0], kr[hh + 0], d);
                    d = fmaf(qr[hh + 1], kr[hh + 1], d);
                    d = fmaf(qr[hh + 2], kr[hh + 2], d);
                    d = fmaf(qr[hh + 3], kr[hh + 3], d);
                }
                d *= SCALE;
                mx = fmaxf(mx, d);
            }
            sc[i] = d;
        }
#pragma unroll
        for (int off = 16; off > 0; off >>= 1)
            mx = fmaxf(mx, __shfl_xor_sync(0xffffffffu, mx, off));

        float sum = 0.f;
#pragma unroll
        for (int i = 0; i < 3; i++) {
            int s = lane + 32 * i;
            if (s < ns) {
                float p = __expf(sc[i] - mx);
                wrow[s] = p;
                sum += p;
            }
        }
#pragma unroll
        for (int off = 16; off > 0; off >>= 1)
            sum += __shfl_xor_sync(0xffffffffu, sum, off);
        const float inv = 1.f / sum;
        __syncwarp();

        // output: lane handles h = lane and lane+32
        float o0 = 0.f, o1 = 0.f;
        for (int s = 0; s < ns; s++) {
            const float p = wrow[s];
            o0 = fmaf(p, vs[s * KPAD + lane],      o0);
            o1 = fmaf(p, vs[s * KPAD + lane + 32], o1);
        }
        float* orow = out + ((size_t)b * T + t) * H;
        orow[lane]      = o0 * inv;
        orow[lane + 32] = o1 * inv;
        __syncwarp();   // wrow reused next iteration
    }
}

extern "C" void kernel_launch(void* const* d_in, const int* in_sizes, int n_in,
                              void* d_out, int out_size)
{
    const float* x  = (const float*)d_in[0];
    const float* Wk = (const float*)d_in[1];
    const float* Wq = (const float*)d_in[2];
    const float* Wv = (const float*)d_in[3];
    float* out = (float*)d_out;

    static bool attr_set = false;
    if (!attr_set) {
        cudaFuncSetAttribute(head_attn_kernel,
                             cudaFuncAttributeMaxDynamicSharedMemorySize, SMEM_BYTES);
        attr_set = true;
    }
    head_attn_kernel<<<BATCH, NTHREADS, SMEM_BYTES>>>(x, Wk, Wq, Wv, out);
}

// round 3
// speedup vs baseline: 1.4068x; 1.4068x over previous
#include <cuda_runtime.h>
#include <cuda_fp16.h>
#include <cstdint>
#include <math.h>

#define BATCH 4096
#define T 96
#define C 256
#define H 64
#define SCALE 0.0625f
#define NT 512

// strides (fp16 elements unless noted)
#define XS 264
#define WS 72
#define KS 72
#define PS 104
#define SS 100   // fp32 elements

// smem byte offsets
#define XH_OFF 0
#define XL_OFF 50688
#define WH_OFF 101376
#define WL_OFF 138240
// phase 2 (reuses phase-1 space after x/W are dead)
#define KH_OFF 0
#define KL_OFF 13824
#define QH_OFF 27648
#define QL_OFF 41472
#define VH_OFF 55296
#define VL_OFF 69120
#define SF_OFF 82944
#define PH_OFF 121344
#define PL_OFF 141312
#define INV_OFF 161280
#define SMEM_BYTES 175104

__device__ __forceinline__ uint32_t smem_u32(const void* p) {
    uint32_t a;
    asm("{ .reg .u64 t; cvta.to.shared.u64 t, %1; cvt.u32.u64 %0, t; }" : "=r"(a) : "l"(p));
    return a;
}

__device__ __forceinline__ void ldsm_x4(unsigned* r, uint32_t addr) {
    asm volatile("ldmatrix.sync.aligned.m8n8.x4.shared.b16 {%0,%1,%2,%3}, [%4];"
                 : "=r"(r[0]), "=r"(r[1]), "=r"(r[2]), "=r"(r[3]) : "r"(addr));
}
__device__ __forceinline__ void ldsm_x2(unsigned* r, uint32_t addr) {
    asm volatile("ldmatrix.sync.aligned.m8n8.x2.shared.b16 {%0,%1}, [%2];"
                 : "=r"(r[0]), "=r"(r[1]) : "r"(addr));
}
__device__ __forceinline__ void ldsm_x2t(unsigned* r, uint32_t addr) {
    asm volatile("ldmatrix.sync.aligned.m8n8.x2.trans.shared.b16 {%0,%1}, [%2];"
                 : "=r"(r[0]), "=r"(r[1]) : "r"(addr));
}
__device__ __forceinline__ void mma16816(float* d, const unsigned* a, const unsigned* b) {
    asm volatile("mma.sync.aligned.m16n8k16.row.col.f32.f16.f16.f32 "
                 "{%0,%1,%2,%3}, {%4,%5,%6,%7}, {%8,%9}, {%0,%1,%2,%3};"
                 : "+f"(d[0]), "+f"(d[1]), "+f"(d[2]), "+f"(d[3])
                 : "r"(a[0]), "r"(a[1]), "r"(a[2]), "r"(a[3]), "r"(b[0]), "r"(b[1]));
}

__device__ __forceinline__ void split(float f, uint16_t& h, uint16_t& l) {
    __half hh = __float2half_rn(f);
    h = __half_as_ushort(hh);
    l = __half_as_ushort(__float2half_rn(f - __half2float(hh)));
}

__device__ __forceinline__ void load_w_tile(char* smem, const float* __restrict__ W, int tid) {
#pragma unroll
    for (int i = 0; i < 8; i++) {
        int idx = tid + i * NT;          // 0..4095 float4's
        int row = idx >> 4;              // 0..255
        int c4  = idx & 15;
        float4 v = *(const float4*)&W[row * H + c4 * 4];
        uint16_t h0, l0, h1, l1, h2, l2, h3, l3;
        split(v.x, h0, l0); split(v.y, h1, l1);
        split(v.z, h2, l2); split(v.w, h3, l3);
        uint32_t off = (uint32_t)(row * WS + c4 * 4) * 2u;
        *(uint2*)(smem + WH_OFF + off) =
            make_uint2((uint32_t)h0 | ((uint32_t)h1 << 16), (uint32_t)h2 | ((uint32_t)h3 << 16));
        *(uint2*)(smem + WL_OFF + off) =
            make_uint2((uint32_t)l0 | ((uint32_t)l1 << 16), (uint32_t)l2 | ((uint32_t)l3 << 16));
    }
}

__global__ __launch_bounds__(NT, 1)
void head_attn_mma(const float* __restrict__ x,
                   const float* __restrict__ Wk,
                   const float* __restrict__ Wq,
                   const float* __restrict__ Wv,
                   float* __restrict__ out)
{
    extern __shared__ char smem[];
    const uint32_t sb = smem_u32(smem);
    const int tid  = threadIdx.x;
    const int w    = tid >> 5;
    const int lane = tid & 31;
    const int b    = blockIdx.x;

    // ---------- load x [96][256] fp32 -> hi/lo fp16 smem ----------
    {
        const float* xb = x + (size_t)b * T * C;
#pragma unroll
        for (int i = 0; i < 12; i++) {
            int idx = tid + i * NT;       // 0..6143 float4's
            int row = idx >> 6;           // 0..95
            int c4  = idx & 63;
            float4 v = *(const float4*)&xb[row * C + c4 * 4];
            uint16_t h0, l0, h1, l1, h2, l2, h3, l3;
            split(v.x, h0, l0); split(v.y, h1, l1);
            split(v.z, h2, l2); split(v.w, h3, l3);
            uint32_t off = (uint32_t)(row * XS + c4 * 4) * 2u;
            *(uint2*)(smem + XH_OFF + off) =
                make_uint2((uint32_t)h0 | ((uint32_t)h1 << 16), (uint32_t)h2 | ((uint32_t)h3 << 16));
            *(uint2*)(smem + XL_OFF + off) =
                make_uint2((uint32_t)l0 | ((uint32_t)l1 << 16), (uint32_t)l2 | ((uint32_t)l3 << 16));
        }
    }
    load_w_tile(smem, Wk, tid);
    __syncthreads();

    // ---------- phase 1: projections via mma ----------
    // warp w: m-group mg = w>>3 (rows mg*48 + mi*16), n-block ng = w&7 (cols ng*8)
    const int mg = w >> 3, ng = w & 7;
    float acc[3][3][4];
#pragma unroll
    for (int a = 0; a < 3; a++)
#pragma unroll
        for (int m = 0; m < 3; m++)
#pragma unroll
            for (int i = 0; i < 4; i++) acc[a][m][i] = 0.f;

    for (int wmat = 0; wmat < 3; wmat++) {
#pragma unroll
        for (int p = 0; p < 3; p++) {
            const uint32_t ab = sb + (p == 1 ? XL_OFF : XH_OFF);
            const uint32_t bb = sb + (p == 2 ? WL_OFF : WH_OFF);
#pragma unroll 4
            for (int k = 0; k < 16; k++) {
                const int k0 = k * 16;
                unsigned bf[2];
                ldsm_x2t(bf, bb + (uint32_t)((k0 + (lane & 15)) * WS + ng * 8) * 2u);
#pragma unroll
                for (int mi = 0; mi < 3; mi++) {
                    unsigned af[4];
                    ldsm_x4(af, ab + (uint32_t)((mg * 48 + mi * 16 + (lane & 15)) * XS
                                                + k0 + 8 * (lane >> 4)) * 2u);
                    mma16816(acc[wmat][mi], af, bf);
                }
            }
        }
        __syncthreads();                 // all warps done reading W tile
        if (wmat == 0) { load_w_tile(smem, Wq, tid); __syncthreads(); }
        else if (wmat == 1) { load_w_tile(smem, Wv, tid); __syncthreads(); }
    }
    // last __syncthreads above also guards overwriting the x region below

    // ---------- spill k,q,v to hi/lo fp16 tiles ----------
#pragma unroll
    for (int wmat = 0; wmat < 3; wmat++) {
        char* hb = smem + (wmat == 0 ? KH_OFF : (wmat == 1 ? QH_OFF : VH_OFF));
        char* lb = smem + (wmat == 0 ? KL_OFF : (wmat == 1 ? QL_OFF : VL_OFF));
#pragma unroll
        for (int mi = 0; mi < 3; mi++) {
            const int r0 = mg * 48 + mi * 16 + (lane >> 2);
            const int c0 = ng * 8 + 2 * (lane & 3);
            uint16_t h0, l0, h1, l1;
            split(acc[wmat][mi][0], h0, l0); split(acc[wmat][mi][1], h1, l1);
            *(uint32_t*)(hb + (r0 * KS + c0) * 2) = (uint32_t)h0 | ((uint32_t)h1 << 16);
            *(uint32_t*)(lb + (r0 * KS + c0) * 2) = (uint32_t)l0 | ((uint32_t)l1 << 16);
            split(acc[wmat][mi][2], h0, l0); split(acc[wmat][mi][3], h1, l1);
            *(uint32_t*)(hb + ((r0 + 8) * KS + c0) * 2) = (uint32_t)h0 | ((uint32_t)h1 << 16);
            *(uint32_t*)(lb + ((r0 + 8) * KS + c0) * 2) = (uint32_t)l0 | ((uint32_t)l1 << 16);
        }
    }
    __syncthreads();

    // ---------- phase 2: scores S = q @ k^T * SCALE ----------
    {
        float* SF = (float*)(smem + SF_OFF);
        for (int blk = w; blk < 72; blk += 16) {
            const int mt = blk / 12, nb = blk % 12;
            float s4[4] = {0.f, 0.f, 0.f, 0.f};
#pragma unroll
            for (int p = 0; p < 3; p++) {
                const uint32_t ab = sb + (p == 1 ? QL_OFF : QH_OFF);
                const uint32_t bb = sb + (p == 2 ? KL_OFF : KH_OFF);
#pragma unroll
                for (int k = 0; k < 4; k++) {
                    const int k0 = k * 16;
                    unsigned af[4], bf[2];
                    ldsm_x4(af, ab + (uint32_t)((mt * 16 + (lane & 15)) * KS
                                                + k0 + 8 * (lane >> 4)) * 2u);
                    ldsm_x2(bf, bb + (uint32_t)((nb * 8 + (lane & 7)) * KS
                                                + k0 + 8 * ((lane >> 3) & 1)) * 2u);
                    mma16816(s4, af, bf);
                }
            }
            const int r0 = mt * 16 + (lane >> 2), c0 = nb * 8 + 2 * (lane & 3);
            SF[r0 * SS + c0]           = s4[0] * SCALE;
            SF[r0 * SS + c0 + 1]       = s4[1] * SCALE;
            SF[(r0 + 8) * SS + c0]     = s4[2] * SCALE;
            SF[(r0 + 8) * SS + c0 + 1] = s4[3] * SCALE;
        }
    }
    __syncthreads();

    // ---------- softmax (causal), P -> hi/lo fp16, inv -> smem ----------
    {
        const float* SF = (const float*)(smem + SF_OFF);
        uint16_t* PH = (uint16_t*)(smem + PH_OFF);
        uint16_t* PL = (uint16_t*)(smem + PL_OFF);
        float* INV = (float*)(smem + INV_OFF);
        for (int t = w; t < T; t += 16) {
            const float* row = SF + t * SS;
            float v0 = (lane <= t)      ? row[lane]      : -1e30f;
            float v1 = (lane + 32 <= t) ? row[lane + 32] : -1e30f;
            float v2 = (lane + 64 <= t) ? row[lane + 64] : -1e30f;
            float mx = fmaxf(v0, fmaxf(v1, v2));
#pragma unroll
            for (int off = 16; off > 0; off >>= 1)
                mx = fmaxf(mx, __shfl_xor_sync(0xffffffffu, mx, off));
            float p0 = (lane <= t)      ? __expf(v0 - mx) : 0.f;
            float p1 = (lane + 32 <= t) ? __expf(v1 - mx) : 0.f;
            float p2 = (lane + 64 <= t) ? __expf(v2 - mx) : 0.f;
            float sum = p0 + p1 + p2;
#pragma unroll
            for (int off = 16; off > 0; off >>= 1)
                sum += __shfl_xor_sync(0xffffffffu, sum, off);
            if (lane == 0) INV[t] = 1.f / sum;
            uint16_t h, l;
            split(p0, h, l); PH[t * PS + lane]      = h; PL[t * PS + lane]      = l;
            split(p1, h, l); PH[t * PS + lane + 32] = h; PL[t * PS + lane + 32] = l;
            split(p2, h, l); PH[t * PS + lane + 64] = h; PL[t * PS + lane + 64] = l;
        }
    }
    __syncthreads();

    // ---------- phase 3: O = P @ v, scale by inv, store ----------
    {
        const float* INV = (const float*)(smem + INV_OFF);
        for (int blk = w; blk < 48; blk += 16) {
            const int mt = blk / 8, nb = blk % 8;
            float o4[4] = {0.f, 0.f, 0.f, 0.f};
#pragma unroll
            for (int p = 0; p < 3; p++) {
                const uint32_t ab = sb + (p == 1 ? PL_OFF : PH_OFF);
                const uint32_t bb = sb + (p == 2 ? VL_OFF : VH_OFF);
#pragma unroll
                for (int k = 0; k < 6; k++) {
                    const int k0 = k * 16;
                    unsigned af[4], bf[2];
                    ldsm_x4(af, ab + (uint32_t)((mt * 16 + (lane & 15)) * PS
                                                + k0 + 8 * (lane >> 4)) * 2u);
                    ldsm_x2t(bf, bb + (uint32_t)((k0 + (lane & 15)) * KS + nb * 8) * 2u);
                    mma16816(o4, af, bf);
                }
            }
            const int r0 = mt * 16 + (lane >> 2), c0 = nb * 8 + 2 * (lane & 3);
            const float i0 = INV[r0], i1 = INV[r0 + 8];
            float* ob = out + (size_t)b * T * H;
            *(float2*)&ob[r0 * H + c0]       = make_float2(o4[0] * i0, o4[1] * i0);
            *(float2*)&ob[(r0 + 8) * H + c0] = make_float2(o4[2] * i1, o4[3] * i1);
        }
    }
}

extern "C" void kernel_launch(void* const* d_in, const int* in_sizes, int n_in,
                              void* d_out, int out_size)
{
    const float* x  = (const float*)d_in[0];
    const float* Wk = (const float*)d_in[1];
    const float* Wq = (const float*)d_in[2];
    const float* Wv = (const float*)d_in[3];
    float* out = (float*)d_out;

    static bool attr_set = false;
    if (!attr_set) {
        cudaFuncSetAttribute(head_attn_mma,
                             cudaFuncAttributeMaxDynamicSharedMemorySize, SMEM_BYTES);
        attr_set = true;
    }
    head_attn_mma<<<BATCH, NT, SMEM_BYTES>>>(x, Wk, Wq, Wv, out);
}

// round 7
// speedup vs baseline: 2.1474x; 1.5264x over previous
#include <cuda_runtime.h>
#include <cuda_fp16.h>
#include <cstdint>
#include <math.h>

#define BATCH 4096
#define T 96
#define C 256
#define H 64
#define SCALE 0.0625f
#define NT 512

// element strides
#define XS 264
#define WS 72
#define KS 72
#define PS 104

// smem byte offsets
#define XH_OFF 0
#define XL_OFF 50688            // x ends 101376
// after phase 1 (overlays x region):
#define KH_OFF 0
#define KL_OFF 13824
#define QH_OFF 27648
#define QL_OFF 41472
#define VH_OFF 55296
#define VL_OFF 69120            // ends 82944
// W chunk region (3 W, each hi 18432 + lo 18432)
#define WB_OFF 101376
#define WBLK   36864            // per-W block (hi+lo)
#define WLO    18432
// phase 2 (overlays W region):
#define PH_OFF 101376
#define PL_OFF 121344
#define INV_OFF 141312
#define SMEM_BYTES 211968

__device__ __forceinline__ uint32_t smem_u32(const void* p) {
    uint32_t a;
    asm("{ .reg .u64 t; cvta.to.shared.u64 t, %1; cvt.u32.u64 %0, t; }" : "=r"(a) : "l"(p));
    return a;
}
__device__ __forceinline__ void ldsm_x4(unsigned* r, uint32_t addr) {
    asm volatile("ldmatrix.sync.aligned.m8n8.x4.shared.b16 {%0,%1,%2,%3}, [%4];"
                 : "=r"(r[0]), "=r"(r[1]), "=r"(r[2]), "=r"(r[3]) : "r"(addr));
}
__device__ __forceinline__ void ldsm_x4t(unsigned* r, uint32_t addr) {
    asm volatile("ldmatrix.sync.aligned.m8n8.x4.trans.shared.b16 {%0,%1,%2,%3}, [%4];"
                 : "=r"(r[0]), "=r"(r[1]), "=r"(r[2]), "=r"(r[3]) : "r"(addr));
}
__device__ __forceinline__ void mma16816(float* d, const unsigned* a, const unsigned* b) {
    asm volatile("mma.sync.aligned.m16n8k16.row.col.f32.f16.f16.f32 "
                 "{%0,%1,%2,%3}, {%4,%5,%6,%7}, {%8,%9}, {%0,%1,%2,%3};"
                 : "+f"(d[0]), "+f"(d[1]), "+f"(d[2]), "+f"(d[3])
                 : "r"(a[0]), "r"(a[1]), "r"(a[2]), "r"(a[3]), "r"(b[0]), "r"(b[1]));
}
__device__ __forceinline__ void split(float f, uint16_t& h, uint16_t& l) {
    __half hh = __float2half_rn(f);
    h = __half_as_ushort(hh);
    l = __half_as_ushort(__float2half_rn(f - __half2float(hh)));
}
__device__ __forceinline__ uint32_t pack2(float a, float b) {
    uint16_t ha, la, hb, lb;
    (void)la; (void)lb;
    __half x = __float2half_rn(a), y = __float2half_rn(b);
    ha = __half_as_ushort(x); hb = __half_as_ushort(y);
    return (uint32_t)ha | ((uint32_t)hb << 16);
}

__global__ __launch_bounds__(NT, 1)
void head_attn_v4(const float* __restrict__ x,
                  const float* __restrict__ Wk,
                  const float* __restrict__ Wq,
                  const float* __restrict__ Wv,
                  float* __restrict__ out)
{
    extern __shared__ char smem[];
    const uint32_t sb = smem_u32(smem);
    const int tid  = threadIdx.x;
    const int w    = tid >> 5;
    const int lane = tid & 31;
    const int b    = blockIdx.x;

    // ---------------- stage x (hi/lo fp16) + W chunk 0 ----------------
    {
        const float* xb = x + (size_t)b * T * C;
#pragma unroll
        for (int i = 0; i < 12; i++) {
            int idx = tid + i * NT;             // 0..6143 float4
            int row = idx >> 6, c4 = idx & 63;
            float4 v = *(const float4*)&xb[row * C + c4 * 4];
            uint16_t h0, l0, h1, l1, h2, l2, h3, l3;
            split(v.x, h0, l0); split(v.y, h1, l1);
            split(v.z, h2, l2); split(v.w, h3, l3);
            uint32_t off = (uint32_t)(row * XS + c4 * 4) * 2u;
            *(uint2*)(smem + XH_OFF + off) =
                make_uint2((uint32_t)h0 | ((uint32_t)h1 << 16), (uint32_t)h2 | ((uint32_t)h3 << 16));
            *(uint2*)(smem + XL_OFF + off) =
                make_uint2((uint32_t)l0 | ((uint32_t)l1 << 16), (uint32_t)l2 | ((uint32_t)l3 << 16));
        }
    }
    const float* Wmats[3] = {Wk, Wq, Wv};
#pragma unroll 1
    for (int i = 0; i < 12; i++) {              // W chunk 0 (k rows 0..127)
        int idx = tid + i * NT;                 // 0..6143 float4
        int wm = idx >> 11;
        int r  = (idx >> 4) & 127;
        int c4 = idx & 15;
        float4 v = *(const float4*)&Wmats[wm][r * H + c4 * 4];
        uint16_t h0, l0, h1, l1, h2, l2, h3, l3;
        split(v.x, h0, l0); split(v.y, h1, l1);
        split(v.z, h2, l2); split(v.w, h3, l3);
        uint32_t off = (uint32_t)(r * WS + c4 * 4) * 2u;
        char* base = smem + WB_OFF + wm * WBLK;
        *(uint2*)(base + off) =
            make_uint2((uint32_t)h0 | ((uint32_t)h1 << 16), (uint32_t)h2 | ((uint32_t)h3 << 16));
        *(uint2*)(base + WLO + off) =
            make_uint2((uint32_t)l0 | ((uint32_t)l1 << 16), (uint32_t)l2 | ((uint32_t)l3 << 16));
    }
    __syncthreads();

    // ---------------- phase 1: projections, warp tile 48x32 ----------------
    // units: w < 12 : wm = w>>2, mh = (w>>1)&1, nh = w&1
    float acc[3][4][4];
#pragma unroll
    for (int mi = 0; mi < 3; mi++)
#pragma unroll
        for (int nb = 0; nb < 4; nb++)
#pragma unroll
            for (int i = 0; i < 4; i++) acc[mi][nb][i] = 0.f;

    const int wm = w >> 2, mh = (w >> 1) & 1, nh = w & 1;
    const uint32_t whb = sb + WB_OFF + wm * WBLK;
    const uint32_t wlb = whb + WLO;

#pragma unroll 1
    for (int chunk = 0; chunk < 2; chunk++) {
        if (w < 12) {
#pragma unroll 1
            for (int kit = 0; kit < 8; kit++) {
                const int k0 = kit * 16;
                const int kg = chunk * 128 + k0;         // global k for x
                unsigned ah[3][4], al[3][4], bh[4][2], bl[4][2];
#pragma unroll
                for (int mi = 0; mi < 3; mi++) {
                    uint32_t ao = (uint32_t)((mh * 48 + mi * 16 + (lane & 15)) * XS
                                             + kg + 8 * (lane >> 4)) * 2u;
                    ldsm_x4(ah[mi], sb + XH_OFF + ao);
                    ldsm_x4(al[mi], sb + XL_OFF + ao);
                }
#pragma unroll
                for (int t2 = 0; t2 < 2; t2++) {
                    unsigned r4[4];
                    uint32_t bo = (uint32_t)((k0 + (lane & 15)) * WS
                                             + nh * 32 + t2 * 16 + 8 * (lane >> 4)) * 2u;
                    ldsm_x4t(r4, whb + bo);
                    bh[2 * t2][0] = r4[0]; bh[2 * t2][1] = r4[1];
                    bh[2 * t2 + 1][0] = r4[2]; bh[2 * t2 + 1][1] = r4[3];
                    ldsm_x4t(r4, wlb + bo);
                    bl[2 * t2][0] = r4[0]; bl[2 * t2][1] = r4[1];
                    bl[2 * t2 + 1][0] = r4[2]; bl[2 * t2 + 1][1] = r4[3];
                }
#pragma unroll
                for (int mi = 0; mi < 3; mi++)
#pragma unroll
                    for (int nb = 0; nb < 4; nb++) {
                        mma16816(acc[mi][nb], ah[mi], bh[nb]);
                        mma16816(acc[mi][nb], al[mi], bh[nb]);
                        mma16816(acc[mi][nb], ah[mi], bl[nb]);
                    }
            }
        }
        __syncthreads();
        if (chunk == 0) {
            // load W chunk 1 (k rows 128..255) into same region
#pragma unroll 1
            for (int i = 0; i < 12; i++) {
                int idx = tid + i * NT;
                int wm2 = idx >> 11;
                int r  = (idx >> 4) & 127;
                int c4 = idx & 15;
                float4 v = *(const float4*)&Wmats[wm2][(128 + r) * H + c4 * 4];
                uint16_t h0, l0, h1, l1, h2, l2, h3, l3;
                split(v.x, h0, l0); split(v.y, h1, l1);
                split(v.z, h2, l2); split(v.w, h3, l3);
                uint32_t off = (uint32_t)(r * WS + c4 * 4) * 2u;
                char* base = smem + WB_OFF + wm2 * WBLK;
                *(uint2*)(base + off) =
                    make_uint2((uint32_t)h0 | ((uint32_t)h1 << 16), (uint32_t)h2 | ((uint32_t)h3 << 16));
                *(uint2*)(base + WLO + off) =
                    make_uint2((uint32_t)l0 | ((uint32_t)l1 << 16), (uint32_t)l2 | ((uint32_t)l3 << 16));
            }
            __syncthreads();
        }
    }

    // ---------------- spill k,q,v (hi/lo) ----------------
    if (w < 12) {
        char* hb = smem + (wm == 0 ? KH_OFF : (wm == 1 ? QH_OFF : VH_OFF));
        char* lb = smem + (wm == 0 ? KL_OFF : (wm == 1 ? QL_OFF : VL_OFF));
#pragma unroll
        for (int mi = 0; mi < 3; mi++) {
            const int r0 = mh * 48 + mi * 16 + (lane >> 2);
            const int c0 = nh * 32 + 2 * (lane & 3);
#pragma unroll
            for (int nb = 0; nb < 4; nb++) {
                uint16_t h0, l0, h1, l1;
                split(acc[mi][nb][0], h0, l0); split(acc[mi][nb][1], h1, l1);
                *(uint32_t*)(hb + (r0 * KS + c0 + nb * 8) * 2) = (uint32_t)h0 | ((uint32_t)h1 << 16);
                *(uint32_t*)(lb + (r0 * KS + c0 + nb * 8) * 2) = (uint32_t)l0 | ((uint32_t)l1 << 16);
                split(acc[mi][nb][2], h0, l0); split(acc[mi][nb][3], h1, l1);
                *(uint32_t*)(hb + ((r0 + 8) * KS + c0 + nb * 8) * 2) = (uint32_t)h0 | ((uint32_t)h1 << 16);
                *(uint32_t*)(lb + ((r0 + 8) * KS + c0 + nb * 8) * 2) = (uint32_t)l0 | ((uint32_t)l1 << 16);
            }
        }
    }
    __syncthreads();

    // ---------------- phases 2+3: warps 0..5, warp owns rows mt*16..mt*16+15 ----------------
    if (w < 6) {
        const int mt = w;
        // ---- scores S = q k^T, full rows in registers ----
        float s[12][4];
#pragma unroll
        for (int nb = 0; nb < 12; nb++)
#pragma unroll
            for (int i = 0; i < 4; i++) s[nb][i] = 0.f;

#pragma unroll 1
        for (int kit = 0; kit < 4; kit++) {
            const int k0 = kit * 16;
            unsigned qh[4], ql[4];
            uint32_t ao = (uint32_t)((mt * 16 + (lane & 15)) * KS + k0 + 8 * (lane >> 4)) * 2u;
            ldsm_x4(qh, sb + QH_OFF + ao);
            ldsm_x4(ql, sb + QL_OFF + ao);
#pragma unroll
            for (int nb2 = 0; nb2 < 6; nb2++) {
                unsigned kh[4], kl[4];
                uint32_t bo = (uint32_t)((nb2 * 16 + (lane & 7) + 8 * (lane >> 4)) * KS
                                         + k0 + 8 * ((lane >> 3) & 1)) * 2u;
                ldsm_x4(kh, sb + KH_OFF + bo);
                ldsm_x4(kl, sb + KL_OFF + bo);
                mma16816(s[2 * nb2],     qh, kh);
                mma16816(s[2 * nb2],     ql, kh);
                mma16816(s[2 * nb2],     qh, kl);
                mma16816(s[2 * nb2 + 1], qh, kh + 2);
                mma16816(s[2 * nb2 + 1], ql, kh + 2);
                mma16816(s[2 * nb2 + 1], qh, kl + 2);
            }
        }

        // ---- in-register causal softmax ----
        const int r0 = mt * 16 + (lane >> 2);
        const int r1 = r0 + 8;
        const int cb = 2 * (lane & 3);
        float mx0 = -1e30f, mx1 = -1e30f;
#pragma unroll
        for (int nb = 0; nb < 12; nb++) {
            int c = nb * 8 + cb;
            if (c     <= r0) mx0 = fmaxf(mx0, s[nb][0]);
            if (c + 1 <= r0) mx0 = fmaxf(mx0, s[nb][1]);
            if (c     <= r1) mx1 = fmaxf(mx1, s[nb][2]);
            if (c + 1 <= r1) mx1 = fmaxf(mx1, s[nb][3]);
        }
        mx0 = fmaxf(mx0, __shfl_xor_sync(0xffffffffu, mx0, 1));
        mx0 = fmaxf(mx0, __shfl_xor_sync(0xffffffffu, mx0, 2));
        mx1 = fmaxf(mx1, __shfl_xor_sync(0xffffffffu, mx1, 1));
        mx1 = fmaxf(mx1, __shfl_xor_sync(0xffffffffu, mx1, 2));
        mx0 *= SCALE; mx1 *= SCALE;

        float sum0 = 0.f, sum1 = 0.f;
        uint16_t* PH = (uint16_t*)(smem + PH_OFF);
        uint16_t* PL = (uint16_t*)(smem + PL_OFF);
#pragma unroll
        for (int nb = 0; nb < 12; nb++) {
            int c = nb * 8 + cb;
            float p0 = (c     <= r0) ? __expf(s[nb][0] * SCALE - mx0) : 0.f;
            float p1 = (c + 1 <= r0) ? __expf(s[nb][1] * SCALE - mx0) : 0.f;
            float p2 = (c     <= r1) ? __expf(s[nb][2] * SCALE - mx1) : 0.f;
            float p3 = (c + 1 <= r1) ? __expf(s[nb][3] * SCALE - mx1) : 0.f;
            sum0 += p0 + p1; sum1 += p2 + p3;
            uint16_t h0, l0, h1, l1;
            split(p0, h0, l0); split(p1, h1, l1);
            *(uint32_t*)&PH[r0 * PS + c] = (uint32_t)h0 | ((uint32_t)h1 << 16);
            *(uint32_t*)&PL[r0 * PS + c] = (uint32_t)l0 | ((uint32_t)l1 << 16);
            split(p2, h0, l0); split(p3, h1, l1);
            *(uint32_t*)&PH[r1 * PS + c] = (uint32_t)h0 | ((uint32_t)h1 << 16);
            *(uint32_t*)&PL[r1 * PS + c] = (uint32_t)l0 | ((uint32_t)l1 << 16);
        }
        sum0 += __shfl_xor_sync(0xffffffffu, sum0, 1);
        sum0 += __shfl_xor_sync(0xffffffffu, sum0, 2);
        sum1 += __shfl_xor_sync(0xffffffffu, sum1, 1);
        sum1 += __shfl_xor_sync(0xffffffffu, sum1, 2);
        const float inv0 = 1.f / sum0;
        const float inv1 = 1.f / sum1;
        __syncwarp();

        // ---- PV: O = P @ v ----
        float o[8][4];
#pragma unroll
        for (int nb = 0; nb < 8; nb++)
#pragma unroll
            for (int i = 0; i < 4; i++) o[nb][i] = 0.f;

#pragma unroll 1
        for (int kit = 0; kit < 6; kit++) {
            const int k0 = kit * 16;
            unsigned ph[4], pl[4];
            uint32_t ao = (uint32_t)((mt * 16 + (lane & 15)) * PS + k0 + 8 * (lane >> 4)) * 2u;
            ldsm_x4(ph, (uint32_t)(sb + PH_OFF) + ao);
            ldsm_x4(pl, (uint32_t)(sb + PL_OFF) + ao);
#pragma unroll
            for (int t2 = 0; t2 < 2; t2++) {
                unsigned vh[4], vl[4];
                uint32_t bo = (uint32_t)((k0 + (lane & 15)) * KS
                                         + t2 * 32 + 16 * (lane >> 4)) * 2u;
                ldsm_x4t(vh, sb + VH_OFF + bo);
                ldsm_x4t(vl, sb + VL_OFF + bo);
                // x4t with 16-col split: r0,r1 = nblk (t2*4+0,+1)? careful: cols t2*32 + 16*(lane>>4)
                // lanes 0-15 -> cols t2*32 .. +15?? -> need col offset 8*(lane>>4) for 8-wide blocks
                mma16816(o[4 * t2],     ph, vh);
                mma16816(o[4 * t2],     pl, vh);
                mma16816(o[4 * t2],     ph, vl);
                mma16816(o[4 * t2 + 2], ph, vh + 2);
                mma16816(o[4 * t2 + 2], pl, vh + 2);
                mma16816(o[4 * t2 + 2], ph, vl + 2);
                uint32_t bo2 = (uint32_t)((k0 + (lane & 15)) * KS
                                          + t2 * 32 + 8 + 16 * (lane >> 4)) * 2u;
                ldsm_x4t(vh, sb + VH_OFF + bo2);
                ldsm_x4t(vl, sb + VL_OFF + bo2);
                mma16816(o[4 * t2 + 1], ph, vh);
                mma16816(o[4 * t2 + 1], pl, vh);
                mma16816(o[4 * t2 + 1], ph, vl);
                mma16816(o[4 * t2 + 3], ph, vh + 2);
                mma16816(o[4 * t2 + 3], pl, vh + 2);
                mma16816(o[4 * t2 + 3], ph, vl + 2);
            }
        }

        // ---- epilogue ----
        float* ob = out + (size_t)b * T * H;
#pragma unroll
        for (int nb = 0; nb < 8; nb++) {
            int c = nb * 8 + cb;
            *(float2*)&ob[r0 * H + c] = make_float2(o[nb][0] * inv0, o[nb][1] * inv0);
            *(float2*)&ob[r1 * H + c] = make_float2(o[nb][2] * inv1, o[nb][3] * inv1);
        }
    }
}

extern "C" void kernel_launch(void* const* d_in, const int* in_sizes, int n_in,
                              void* d_out, int out_size)
{
    const float* x  = (const float*)d_in[0];
    const float* Wk = (const float*)d_in[1];
    const float* Wq = (const float*)d_in[2];
    const float* Wv = (const float*)d_in[3];
    float* out = (float*)d_out;

    static bool attr_set = false;
    if (!attr_set) {
        cudaFuncSetAttribute(head_attn_v4,
                             cudaFuncAttributeMaxDynamicSharedMemorySize, SMEM_BYTES);
        attr_set = true;
    }
    head_attn_v4<<<BATCH, NT, SMEM_BYTES>>>(x, Wk, Wq, Wv, out);
}

// round 8
// speedup vs baseline: 3.8109x; 1.7746x over previous
#include <cuda_runtime.h>
#include <cuda_fp16.h>
#include <cstdint>
#include <math.h>

#define BATCH 4096
#define T 96
#define C 256
#define H 64
#define SCALE 0.0625f
#define NT 256

// element strides (fp16)
#define XS 72
#define WS 72
#define KS 72
#define PS 104

// region A (phase 1), byte offsets
#define XH_OFF 0
#define XL_OFF 13824
#define WB_OFF 27648          // 3 W blocks, each hi 9216 + lo 9216
#define WBLK   18432
#define WLO    9216
// region B (kqv, overlays region A after phase 1)
#define KH_OFF 0
#define KL_OFF 13824
#define QH_OFF 27648
#define QL_OFF 41472
#define VH_OFF 55296
#define VL_OFF 69120
// region C (P, overlays k/q after S is in registers)
#define PH_OFF 0
#define PL_OFF 19968
#define SMEM_BYTES 82944

// -------- W pre-converted to fp16 hi/lo (shared across all CTAs) --------
__device__ __half g_Wh[3][C * H];
__device__ __half g_Wl[3][C * H];

__global__ void convW_kernel(const float* __restrict__ Wk,
                             const float* __restrict__ Wq,
                             const float* __restrict__ Wv)
{
    int idx = blockIdx.x * 256 + threadIdx.x;        // 0..49151
    int wm  = idx >> 14;
    int r   = idx & 16383;
    const float* W = (wm == 0) ? Wk : (wm == 1 ? Wq : Wv);
    float f = W[r];
    __half h = __float2half_rn(f);
    g_Wh[wm][r] = h;
    g_Wl[wm][r] = __float2half_rn(f - __half2float(h));
}

__device__ __forceinline__ uint32_t smem_u32(const void* p) {
    uint32_t a;
    asm("{ .reg .u64 t; cvta.to.shared.u64 t, %1; cvt.u32.u64 %0, t; }" : "=r"(a) : "l"(p));
    return a;
}
__device__ __forceinline__ void ldsm_x4(unsigned* r, uint32_t addr) {
    asm volatile("ldmatrix.sync.aligned.m8n8.x4.shared.b16 {%0,%1,%2,%3}, [%4];"
                 : "=r"(r[0]), "=r"(r[1]), "=r"(r[2]), "=r"(r[3]) : "r"(addr));
}
__device__ __forceinline__ void ldsm_x4t(unsigned* r, uint32_t addr) {
    asm volatile("ldmatrix.sync.aligned.m8n8.x4.trans.shared.b16 {%0,%1,%2,%3}, [%4];"
                 : "=r"(r[0]), "=r"(r[1]), "=r"(r[2]), "=r"(r[3]) : "r"(addr));
}
__device__ __forceinline__ void mma16816(float* d, const unsigned* a, const unsigned* b) {
    asm volatile("mma.sync.aligned.m16n8k16.row.col.f32.f16.f16.f32 "
                 "{%0,%1,%2,%3}, {%4,%5,%6,%7}, {%8,%9}, {%0,%1,%2,%3};"
                 : "+f"(d[0]), "+f"(d[1]), "+f"(d[2]), "+f"(d[3])
                 : "r"(a[0]), "r"(a[1]), "r"(a[2]), "r"(a[3]), "r"(b[0]), "r"(b[1]));
}
__device__ __forceinline__ void split(float f, uint16_t& h, uint16_t& l) {
    __half hh = __float2half_rn(f);
    h = __half_as_ushort(hh);
    l = __half_as_ushort(__float2half_rn(f - __half2float(hh)));
}

__global__ __launch_bounds__(NT, 2)
void head_attn_v5(const float* __restrict__ x,
                  float* __restrict__ out)
{
    extern __shared__ char smem[];
    const uint32_t sb = smem_u32(smem);
    const int tid  = threadIdx.x;
    const int w    = tid >> 5;
    const int lane = tid & 31;
    const int b    = blockIdx.x;

    // warp decomposition for phase 1: mh = w>>2 (m-half), q4 = w&3; 3 units each
    const int mh = w >> 2, q4 = w & 3;

    float acc[3][3][2][4];                 // [unit][mi][nb][4]
#pragma unroll
    for (int j = 0; j < 3; j++)
#pragma unroll
        for (int mi = 0; mi < 3; mi++)
#pragma unroll
            for (int nb = 0; nb < 2; nb++)
#pragma unroll
                for (int i = 0; i < 4; i++) acc[j][mi][nb][i] = 0.f;

    const float* xb = x + (size_t)b * T * C;

    // ---------------- phase 1: 4 K-chunks of 64 ----------------
#pragma unroll 1
    for (int c = 0; c < 4; c++) {
        // stage x chunk [96][64] fp32 -> hi/lo fp16
#pragma unroll
        for (int i = 0; i < 6; i++) {
            int idx = tid + i * NT;                  // 0..1535 float4
            int row = idx >> 4, c4 = idx & 15;
            float4 v = *(const float4*)&xb[row * C + c * 64 + c4 * 4];
            uint16_t h0, l0, h1, l1, h2, l2, h3, l3;
            split(v.x, h0, l0); split(v.y, h1, l1);
            split(v.z, h2, l2); split(v.w, h3, l3);
            uint32_t off = (uint32_t)(row * XS + c4 * 4) * 2u;
            *(uint2*)(smem + XH_OFF + off) =
                make_uint2((uint32_t)h0 | ((uint32_t)h1 << 16), (uint32_t)h2 | ((uint32_t)h3 << 16));
            *(uint2*)(smem + XL_OFF + off) =
                make_uint2((uint32_t)l0 | ((uint32_t)l1 << 16), (uint32_t)l2 | ((uint32_t)l3 << 16));
        }
        // stage W chunk [64][64] x3 (hi/lo), pure uint4 copies
#pragma unroll
        for (int i = 0; i < 12; i++) {
            int idx = tid + i * NT;                  // 0..3071 uint4
            int p   = (i >= 6) ? 1 : 0;              // hi first 1536, lo next
            int jdx = idx - p * 1536;
            int wm2 = jdx >> 9;                      // 512 uint4 per matrix
            int r   = (jdx >> 3) & 63;
            int c8  = jdx & 7;
            const __half* src = (p ? g_Wl[wm2] : g_Wh[wm2]) + (c * 64 + r) * H + c8 * 8;
            uint4 v = *(const uint4*)src;
            *(uint4*)(smem + WB_OFF + wm2 * WBLK + p * WLO + (uint32_t)(r * WS + c8 * 8) * 2u) = v;
        }
        __syncthreads();

        // mma over this chunk
#pragma unroll
        for (int kit = 0; kit < 4; kit++) {
            const int k0 = kit * 16;
            unsigned ah[3][4], al[3][4];
#pragma unroll
            for (int mi = 0; mi < 3; mi++) {
                uint32_t ao = (uint32_t)((mh * 48 + mi * 16 + (lane & 15)) * XS
                                         + k0 + 8 * (lane >> 4)) * 2u;
                ldsm_x4(ah[mi], sb + XH_OFF + ao);
                ldsm_x4(al[mi], sb + XL_OFF + ao);
            }
#pragma unroll
            for (int j = 0; j < 3; j++) {
                const int p  = q4 * 3 + j;
                const int wm = p >> 2, nq = p & 3;
                const uint32_t wb = sb + WB_OFF + wm * WBLK;
                uint32_t bo = (uint32_t)((k0 + (lane & 15)) * WS
                                         + nq * 16 + 8 * (lane >> 4)) * 2u;
                unsigned bh[4], bl[4];
                ldsm_x4t(bh, wb + bo);
                ldsm_x4t(bl, wb + WLO + bo);
#pragma unroll
                for (int mi = 0; mi < 3; mi++)
#pragma unroll
                    for (int nb = 0; nb < 2; nb++) {
                        mma16816(acc[j][mi][nb], ah[mi], bh + 2 * nb);
                        mma16816(acc[j][mi][nb], al[mi], bh + 2 * nb);
                        mma16816(acc[j][mi][nb], ah[mi], bl + 2 * nb);
                    }
            }
        }
        __syncthreads();
    }

    // ---------------- spill k,q,v hi/lo ----------------
#pragma unroll
    for (int j = 0; j < 3; j++) {
        const int p  = q4 * 3 + j;
        const int wm = p >> 2, nq = p & 3;
        char* hb = smem + (wm == 0 ? KH_OFF : (wm == 1 ? QH_OFF : VH_OFF));
        char* lb = hb + 13824;
#pragma unroll
        for (int mi = 0; mi < 3; mi++) {
            const int r0 = mh * 48 + mi * 16 + (lane >> 2);
#pragma unroll
            for (int nb = 0; nb < 2; nb++) {
                const int c0 = nq * 16 + nb * 8 + 2 * (lane & 3);
                uint16_t h0, l0, h1, l1;
                split(acc[j][mi][nb][0], h0, l0); split(acc[j][mi][nb][1], h1, l1);
                *(uint32_t*)(hb + (r0 * KS + c0) * 2) = (uint32_t)h0 | ((uint32_t)h1 << 16);
                *(uint32_t*)(lb + (r0 * KS + c0) * 2) = (uint32_t)l0 | ((uint32_t)l1 << 16);
                split(acc[j][mi][nb][2], h0, l0); split(acc[j][mi][nb][3], h1, l1);
                *(uint32_t*)(hb + ((r0 + 8) * KS + c0) * 2) = (uint32_t)h0 | ((uint32_t)h1 << 16);
                *(uint32_t*)(lb + ((r0 + 8) * KS + c0) * 2) = (uint32_t)l0 | ((uint32_t)l1 << 16);
            }
        }
    }
    __syncthreads();

    // ---------------- phase 2: S = q k^T (warps 0..5, 16 rows each) ----------------
    const int mt = w;
    float s[12][4];
    if (w < 6) {
#pragma unroll
        for (int nb = 0; nb < 12; nb++)
#pragma unroll
            for (int i = 0; i < 4; i++) s[nb][i] = 0.f;
#pragma unroll 1
        for (int kit = 0; kit < 4; kit++) {
            const int k0 = kit * 16;
            unsigned qh[4], ql[4];
            uint32_t ao = (uint32_t)((mt * 16 + (lane & 15)) * KS + k0 + 8 * (lane >> 4)) * 2u;
            ldsm_x4(qh, sb + QH_OFF + ao);
            ldsm_x4(ql, sb + QL_OFF + ao);
#pragma unroll
            for (int nb2 = 0; nb2 < 6; nb2++) {
                unsigned kh[4], kl[4];
                uint32_t bo = (uint32_t)((nb2 * 16 + (lane & 7) + 8 * (lane >> 4)) * KS
                                         + k0 + 8 * ((lane >> 3) & 1)) * 2u;
                ldsm_x4(kh, sb + KH_OFF + bo);
                ldsm_x4(kl, sb + KL_OFF + bo);
                mma16816(s[2 * nb2],     qh, kh);
                mma16816(s[2 * nb2],     ql, kh);
                mma16816(s[2 * nb2],     qh, kl);
                mma16816(s[2 * nb2 + 1], qh, kh + 2);
                mma16816(s[2 * nb2 + 1], ql, kh + 2);
                mma16816(s[2 * nb2 + 1], qh, kl + 2);
            }
        }
    }
    __syncthreads();    // all warps: q,k reads done before P overlays them

    if (w < 6) {
        // ---- in-register causal softmax, P -> hi/lo fp16 (own 16 rows) ----
        const int r0 = mt * 16 + (lane >> 2);
        const int r1 = r0 + 8;
        const int cb = 2 * (lane & 3);
        float mx0 = -1e30f, mx1 = -1e30f;
#pragma unroll
        for (int nb = 0; nb < 12; nb++) {
            int c = nb * 8 + cb;
            if (c     <= r0) mx0 = fmaxf(mx0, s[nb][0]);
            if (c + 1 <= r0) mx0 = fmaxf(mx0, s[nb][1]);
            if (c     <= r1) mx1 = fmaxf(mx1, s[nb][2]);
            if (c + 1 <= r1) mx1 = fmaxf(mx1, s[nb][3]);
        }
        mx0 = fmaxf(mx0, __shfl_xor_sync(0xffffffffu, mx0, 1));
        mx0 = fmaxf(mx0, __shfl_xor_sync(0xffffffffu, mx0, 2));
        mx1 = fmaxf(mx1, __shfl_xor_sync(0xffffffffu, mx1, 1));
        mx1 = fmaxf(mx1, __shfl_xor_sync(0xffffffffu, mx1, 2));
        mx0 *= SCALE; mx1 *= SCALE;

        float sum0 = 0.f, sum1 = 0.f;
        uint16_t* PH = (uint16_t*)(smem + PH_OFF);
        uint16_t* PL = (uint16_t*)(smem + PL_OFF);
#pragma unroll
        for (int nb = 0; nb < 12; nb++) {
            int c = nb * 8 + cb;
            float p0 = (c     <= r0) ? __expf(s[nb][0] * SCALE - mx0) : 0.f;
            float p1 = (c + 1 <= r0) ? __expf(s[nb][1] * SCALE - mx0) : 0.f;
            float p2 = (c     <= r1) ? __expf(s[nb][2] * SCALE - mx1) : 0.f;
            float p3 = (c + 1 <= r1) ? __expf(s[nb][3] * SCALE - mx1) : 0.f;
            sum0 += p0 + p1; sum1 += p2 + p3;
            uint16_t h0, l0, h1, l1;
            split(p0, h0, l0); split(p1, h1, l1);
            *(uint32_t*)&PH[r0 * PS + c] = (uint32_t)h0 | ((uint32_t)h1 << 16);
            *(uint32_t*)&PL[r0 * PS + c] = (uint32_t)l0 | ((uint32_t)l1 << 16);
            split(p2, h0, l0); split(p3, h1, l1);
            *(uint32_t*)&PH[r1 * PS + c] = (uint32_t)h0 | ((uint32_t)h1 << 16);
            *(uint32_t*)&PL[r1 * PS + c] = (uint32_t)l0 | ((uint32_t)l1 << 16);
        }
        sum0 += __shfl_xor_sync(0xffffffffu, sum0, 1);
        sum0 += __shfl_xor_sync(0xffffffffu, sum0, 2);
        sum1 += __shfl_xor_sync(0xffffffffu, sum1, 1);
        sum1 += __shfl_xor_sync(0xffffffffu, sum1, 2);
        const float inv0 = 1.f / sum0;
        const float inv1 = 1.f / sum1;
        __syncwarp();

        // ---- phase 3: O = P @ v (reads own P rows + all v rows) ----
        float o[8][4];
#pragma unroll
        for (int nb = 0; nb < 8; nb++)
#pragma unroll
            for (int i = 0; i < 4; i++) o[nb][i] = 0.f;
#pragma unroll 1
        for (int kit = 0; kit < 6; kit++) {
            const int k0 = kit * 16;
            unsigned ph[4], pl[4];
            uint32_t ao = (uint32_t)((mt * 16 + (lane & 15)) * PS + k0 + 8 * (lane >> 4)) * 2u;
            ldsm_x4(ph, sb + PH_OFF + ao);
            ldsm_x4(pl, sb + PL_OFF + ao);
#pragma unroll
            for (int t2 = 0; t2 < 2; t2++) {
                unsigned vh[4], vl[4];
                uint32_t bo = (uint32_t)((k0 + (lane & 15)) * KS
                                         + t2 * 32 + 16 * (lane >> 4)) * 2u;
                ldsm_x4t(vh, sb + VH_OFF + bo);
                ldsm_x4t(vl, sb + VL_OFF + bo);
                mma16816(o[4 * t2],     ph, vh);
                mma16816(o[4 * t2],     pl, vh);
                mma16816(o[4 * t2],     ph, vl);
                mma16816(o[4 * t2 + 2], ph, vh + 2);
                mma16816(o[4 * t2 + 2], pl, vh + 2);
                mma16816(o[4 * t2 + 2], ph, vl + 2);
                uint32_t bo2 = (uint32_t)((k0 + (lane & 15)) * KS
                                          + t2 * 32 + 8 + 16 * (lane >> 4)) * 2u;
                ldsm_x4t(vh, sb + VH_OFF + bo2);
                ldsm_x4t(vl, sb + VL_OFF + bo2);
                mma16816(o[4 * t2 + 1], ph, vh);
                mma16816(o[4 * t2 + 1], pl, vh);
                mma16816(o[4 * t2 + 1], ph, vl);
                mma16816(o[4 * t2 + 3], ph, vh + 2);
                mma16816(o[4 * t2 + 3], pl, vh + 2);
                mma16816(o[4 * t2 + 3], ph, vl + 2);
            }
        }

        // ---- epilogue ----
        float* ob = out + (size_t)b * T * H;
#pragma unroll
        for (int nb = 0; nb < 8; nb++) {
            int c = nb * 8 + cb;
            *(float2*)&ob[r0 * H + c] = make_float2(o[nb][0] * inv0, o[nb][1] * inv0);
            *(float2*)&ob[r1 * H + c] = make_float2(o[nb][2] * inv1, o[nb][3] * inv1);
        }
    }
}

extern "C" void kernel_launch(void* const* d_in, const int* in_sizes, int n_in,
                              void* d_out, int out_size)
{
    const float* x  = (const float*)d_in[0];
    const float* Wk = (const float*)d_in[1];
    const float* Wq = (const float*)d_in[2];
    const float* Wv = (const float*)d_in[3];
    float* out = (float*)d_out;

    static bool attr_set = false;
    if (!attr_set) {
        cudaFuncSetAttribute(head_attn_v5,
                             cudaFuncAttributeMaxDynamicSharedMemorySize, SMEM_BYTES);
        attr_set = true;
    }
    convW_kernel<<<192, 256>>>(Wk, Wq, Wv);
    head_attn_v5<<<BATCH, NT, SMEM_BYTES>>>(x, out);
}

// round 9
// speedup vs baseline: 4.3965x; 1.1537x over previous
#include <cuda_runtime.h>
#include <cuda_fp16.h>
#include <cstdint>
#include <math.h>

#define BATCH 4096
#define T 96
#define C 256
#define H 64
#define SCALE 0.0625f
#define NT 256

// element strides (fp16)
#define XS 72
#define WS 72
#define KS 72
#define PS 104

// region A (phase 1), byte offsets
#define XH_OFF 0
#define XL_OFF 13824
#define WB_OFF 27648          // 3 W blocks (hi only), 9216 each
#define WBLK   9216
// region B (kqv, overlays region A after phase 1)
#define KH_OFF 0
#define QH_OFF 13824
#define QL_OFF 27648
#define VH_OFF 41472          // ends 55296
// region C (P hi/lo, overlays k/q after S is in registers)
#define PH_OFF 0
#define PL_OFF 19968          // ends 39936 (< VH_OFF) -- v stays live
#define SMEM_BYTES 55296

// -------- W pre-converted to fp16 (shared across all CTAs) --------
__device__ __half g_Wh[3][C * H];

__global__ void convW_kernel(const float* __restrict__ Wk,
                             const float* __restrict__ Wq,
                             const float* __restrict__ Wv)
{
    int idx = blockIdx.x * 256 + threadIdx.x;        // 0..49151
    int wm  = idx >> 14;
    int r   = idx & 16383;
    const float* W = (wm == 0) ? Wk : (wm == 1 ? Wq : Wv);
    g_Wh[wm][r] = __float2half_rn(W[r]);
}

__device__ __forceinline__ uint32_t smem_u32(const void* p) {
    uint32_t a;
    asm("{ .reg .u64 t; cvta.to.shared.u64 t, %1; cvt.u32.u64 %0, t; }" : "=r"(a) : "l"(p));
    return a;
}
__device__ __forceinline__ void ldsm_x4(unsigned* r, uint32_t addr) {
    asm volatile("ldmatrix.sync.aligned.m8n8.x4.shared.b16 {%0,%1,%2,%3}, [%4];"
                 : "=r"(r[0]), "=r"(r[1]), "=r"(r[2]), "=r"(r[3]) : "r"(addr));
}
__device__ __forceinline__ void ldsm_x4t(unsigned* r, uint32_t addr) {
    asm volatile("ldmatrix.sync.aligned.m8n8.x4.trans.shared.b16 {%0,%1,%2,%3}, [%4];"
                 : "=r"(r[0]), "=r"(r[1]), "=r"(r[2]), "=r"(r[3]) : "r"(addr));
}
__device__ __forceinline__ void mma16816(float* d, const unsigned* a, const unsigned* b) {
    asm volatile("mma.sync.aligned.m16n8k16.row.col.f32.f16.f16.f32 "
                 "{%0,%1,%2,%3}, {%4,%5,%6,%7}, {%8,%9}, {%0,%1,%2,%3};"
                 : "+f"(d[0]), "+f"(d[1]), "+f"(d[2]), "+f"(d[3])
                 : "r"(a[0]), "r"(a[1]), "r"(a[2]), "r"(a[3]), "r"(b[0]), "r"(b[1]));
}
__device__ __forceinline__ void split(float f, uint16_t& h, uint16_t& l) {
    __half hh = __float2half_rn(f);
    h = __half_as_ushort(hh);
    l = __half_as_ushort(__float2half_rn(f - __half2float(hh)));
}
__device__ __forceinline__ uint32_t pack2h(float a, float b) {
    return (uint32_t)__half_as_ushort(__float2half_rn(a))
         | ((uint32_t)__half_as_ushort(__float2half_rn(b)) << 16);
}

__global__ __launch_bounds__(NT, 2)
void head_attn_v6(const float* __restrict__ x,
                  float* __restrict__ out)
{
    extern __shared__ char smem[];
    const uint32_t sb = smem_u32(smem);
    const int tid  = threadIdx.x;
    const int w    = tid >> 5;
    const int lane = tid & 31;
    const int b    = blockIdx.x;

    // warp decomposition for phase 1: mh = w>>2 (m-half), q4 = w&3; 3 units each
    const int mh = w >> 2, q4 = w & 3;

    float acc[3][3][2][4];                 // [unit][mi][nb][4]
#pragma unroll
    for (int j = 0; j < 3; j++)
#pragma unroll
        for (int mi = 0; mi < 3; mi++)
#pragma unroll
            for (int nb = 0; nb < 2; nb++)
#pragma unroll
                for (int i = 0; i < 4; i++) acc[j][mi][nb][i] = 0.f;

    const float* xb = x + (size_t)b * T * C;

    // ---------------- phase 1: 4 K-chunks of 64 ----------------
#pragma unroll 1
    for (int c = 0; c < 4; c++) {
        // stage x chunk [96][64] fp32 -> hi/lo fp16
#pragma unroll
        for (int i = 0; i < 6; i++) {
            int idx = tid + i * NT;                  // 0..1535 float4
            int row = idx >> 4, c4 = idx & 15;
            float4 v = *(const float4*)&xb[row * C + c * 64 + c4 * 4];
            uint16_t h0, l0, h1, l1, h2, l2, h3, l3;
            split(v.x, h0, l0); split(v.y, h1, l1);
            split(v.z, h2, l2); split(v.w, h3, l3);
            uint32_t off = (uint32_t)(row * XS + c4 * 4) * 2u;
            *(uint2*)(smem + XH_OFF + off) =
                make_uint2((uint32_t)h0 | ((uint32_t)h1 << 16), (uint32_t)h2 | ((uint32_t)h3 << 16));
            *(uint2*)(smem + XL_OFF + off) =
                make_uint2((uint32_t)l0 | ((uint32_t)l1 << 16), (uint32_t)l2 | ((uint32_t)l3 << 16));
        }
        // stage W chunk [64][64] x3 (hi only), pure uint4 copies
#pragma unroll
        for (int i = 0; i < 6; i++) {
            int idx = tid + i * NT;                  // 0..1535 uint4
            int wm2 = idx >> 9;                      // 512 uint4 per matrix
            int r   = (idx >> 3) & 63;
            int c8  = idx & 7;
            uint4 v = *(const uint4*)(g_Wh[wm2] + (c * 64 + r) * H + c8 * 8);
            *(uint4*)(smem + WB_OFF + wm2 * WBLK + (uint32_t)(r * WS + c8 * 8) * 2u) = v;
        }
        __syncthreads();

        // mma over this chunk: 2-pass (xh + xl) * Wh
#pragma unroll
        for (int kit = 0; kit < 4; kit++) {
            const int k0 = kit * 16;
            unsigned ah[3][4], al[3][4];
#pragma unroll
            for (int mi = 0; mi < 3; mi++) {
                uint32_t ao = (uint32_t)((mh * 48 + mi * 16 + (lane & 15)) * XS
                                         + k0 + 8 * (lane >> 4)) * 2u;
                ldsm_x4(ah[mi], sb + XH_OFF + ao);
                ldsm_x4(al[mi], sb + XL_OFF + ao);
            }
#pragma unroll
            for (int j = 0; j < 3; j++) {
                const int p  = q4 * 3 + j;
                const int wm = p >> 2, nq = p & 3;
                uint32_t bo = (uint32_t)((k0 + (lane & 15)) * WS
                                         + nq * 16 + 8 * (lane >> 4)) * 2u;
                unsigned bh[4];
                ldsm_x4t(bh, sb + WB_OFF + wm * WBLK + bo);
#pragma unroll
                for (int mi = 0; mi < 3; mi++)
#pragma unroll
                    for (int nb = 0; nb < 2; nb++) {
                        mma16816(acc[j][mi][nb], ah[mi], bh + 2 * nb);
                        mma16816(acc[j][mi][nb], al[mi], bh + 2 * nb);
                    }
            }
        }
        __syncthreads();
    }

    // ---------------- spill: q hi/lo, k hi, v hi ----------------
#pragma unroll
    for (int j = 0; j < 3; j++) {
        const int p  = q4 * 3 + j;
        const int wm = p >> 2, nq = p & 3;
        char* hb = smem + (wm == 0 ? KH_OFF : (wm == 1 ? QH_OFF : VH_OFF));
#pragma unroll
        for (int mi = 0; mi < 3; mi++) {
            const int r0 = mh * 48 + mi * 16 + (lane >> 2);
#pragma unroll
            for (int nb = 0; nb < 2; nb++) {
                const int c0 = nq * 16 + nb * 8 + 2 * (lane & 3);
                if (wm == 1) {
                    char* lb = smem + QL_OFF;
                    uint16_t h0, l0, h1, l1;
                    split(acc[j][mi][nb][0], h0, l0); split(acc[j][mi][nb][1], h1, l1);
                    *(uint32_t*)(hb + (r0 * KS + c0) * 2) = (uint32_t)h0 | ((uint32_t)h1 << 16);
                    *(uint32_t*)(lb + (r0 * KS + c0) * 2) = (uint32_t)l0 | ((uint32_t)l1 << 16);
                    split(acc[j][mi][nb][2], h0, l0); split(acc[j][mi][nb][3], h1, l1);
                    *(uint32_t*)(hb + ((r0 + 8) * KS + c0) * 2) = (uint32_t)h0 | ((uint32_t)h1 << 16);
                    *(uint32_t*)(lb + ((r0 + 8) * KS + c0) * 2) = (uint32_t)l0 | ((uint32_t)l1 << 16);
                } else {
                    *(uint32_t*)(hb + (r0 * KS + c0) * 2) =
                        pack2h(acc[j][mi][nb][0], acc[j][mi][nb][1]);
                    *(uint32_t*)(hb + ((r0 + 8) * KS + c0) * 2) =
                        pack2h(acc[j][mi][nb][2], acc[j][mi][nb][3]);
                }
            }
        }
    }
    __syncthreads();

    // ---------------- phase 2: S = q k^T (warps 0..5, causal-trimmed) ----------------
    const int mt = w;
    float s[12][4];
    if (w < 6) {
#pragma unroll
        for (int nb = 0; nb < 12; nb++)
#pragma unroll
            for (int i = 0; i < 4; i++) s[nb][i] = 0.f;
#pragma unroll 1
        for (int kit = 0; kit < 4; kit++) {
            const int k0 = kit * 16;
            unsigned qh[4], ql[4];
            uint32_t ao = (uint32_t)((mt * 16 + (lane & 15)) * KS + k0 + 8 * (lane >> 4)) * 2u;
            ldsm_x4(qh, sb + QH_OFF + ao);
            ldsm_x4(ql, sb + QL_OFF + ao);
#pragma unroll 1
            for (int nb2 = 0; nb2 <= mt; nb2++) {    // causal: cols <= mt*16+15
                unsigned kh[4];
                uint32_t bo = (uint32_t)((nb2 * 16 + (lane & 7) + 8 * (lane >> 4)) * KS
                                         + k0 + 8 * ((lane >> 3) & 1)) * 2u;
                ldsm_x4(kh, sb + KH_OFF + bo);
                mma16816(s[2 * nb2],     qh, kh);
                mma16816(s[2 * nb2],     ql, kh);
                mma16816(s[2 * nb2 + 1], qh, kh + 2);
                mma16816(s[2 * nb2 + 1], ql, kh + 2);
            }
        }
    }
    __syncthreads();    // all warps: q,k reads done before P overlays them

    if (w < 6) {
        // ---- in-register causal softmax, P -> hi/lo fp16 (own 16 rows) ----
        const int r0 = mt * 16 + (lane >> 2);
        const int r1 = r0 + 8;
        const int cb = 2 * (lane & 3);
        float mx0 = -1e30f, mx1 = -1e30f;
#pragma unroll
        for (int nb = 0; nb < 12; nb++) {
            int c = nb * 8 + cb;
            if (c     <= r0) mx0 = fmaxf(mx0, s[nb][0]);
            if (c + 1 <= r0) mx0 = fmaxf(mx0, s[nb][1]);
            if (c     <= r1) mx1 = fmaxf(mx1, s[nb][2]);
            if (c + 1 <= r1) mx1 = fmaxf(mx1, s[nb][3]);
        }
        mx0 = fmaxf(mx0, __shfl_xor_sync(0xffffffffu, mx0, 1));
        mx0 = fmaxf(mx0, __shfl_xor_sync(0xffffffffu, mx0, 2));
        mx1 = fmaxf(mx1, __shfl_xor_sync(0xffffffffu, mx1, 1));
        mx1 = fmaxf(mx1, __shfl_xor_sync(0xffffffffu, mx1, 2));
        mx0 *= SCALE; mx1 *= SCALE;

        float sum0 = 0.f, sum1 = 0.f;
        uint16_t* PH = (uint16_t*)(smem + PH_OFF);
        uint16_t* PL = (uint16_t*)(smem + PL_OFF);
#pragma unroll
        for (int nb = 0; nb < 12; nb++) {
            int c = nb * 8 + cb;
            float p0 = (c     <= r0) ? __expf(s[nb][0] * SCALE - mx0) : 0.f;
            float p1 = (c + 1 <= r0) ? __expf(s[nb][1] * SCALE - mx0) : 0.f;
            float p2 = (c     <= r1) ? __expf(s[nb][2] * SCALE - mx1) : 0.f;
            float p3 = (c + 1 <= r1) ? __expf(s[nb][3] * SCALE - mx1) : 0.f;
            sum0 += p0 + p1; sum1 += p2 + p3;
            uint16_t h0, l0, h1, l1;
            split(p0, h0, l0); split(p1, h1, l1);
            *(uint32_t*)&PH[r0 * PS + c] = (uint32_t)h0 | ((uint32_t)h1 << 16);
            *(uint32_t*)&PL[r0 * PS + c] = (uint32_t)l0 | ((uint32_t)l1 << 16);
            split(p2, h0, l0); split(p3, h1, l1);
            *(uint32_t*)&PH[r1 * PS + c] = (uint32_t)h0 | ((uint32_t)h1 << 16);
            *(uint32_t*)&PL[r1 * PS + c] = (uint32_t)l0 | ((uint32_t)l1 << 16);
        }
        sum0 += __shfl_xor_sync(0xffffffffu, sum0, 1);
        sum0 += __shfl_xor_sync(0xffffffffu, sum0, 2);
        sum1 += __shfl_xor_sync(0xffffffffu, sum1, 1);
        sum1 += __shfl_xor_sync(0xffffffffu, sum1, 2);
        const float inv0 = 1.f / sum0;
        const float inv1 = 1.f / sum1;
        __syncwarp();

        // ---- phase 3: O = P @ v (2-pass: (Ph+Pl)*vh) ----
        float o[8][4];
#pragma unroll
        for (int nb = 0; nb < 8; nb++)
#pragma unroll
            for (int i = 0; i < 4; i++) o[nb][i] = 0.f;
#pragma unroll 1
        for (int kit = 0; kit < 6; kit++) {
            const int k0 = kit * 16;
            unsigned ph[4], pl[4];
            uint32_t ao = (uint32_t)((mt * 16 + (lane & 15)) * PS + k0 + 8 * (lane >> 4)) * 2u;
            ldsm_x4(ph, sb + PH_OFF + ao);
            ldsm_x4(pl, sb + PL_OFF + ao);
#pragma unroll
            for (int t2 = 0; t2 < 2; t2++) {
                unsigned vh[4];
                uint32_t bo = (uint32_t)((k0 + (lane & 15)) * KS
                                         + t2 * 32 + 16 * (lane >> 4)) * 2u;
                ldsm_x4t(vh, sb + VH_OFF + bo);
                mma16816(o[4 * t2],     ph, vh);
                mma16816(o[4 * t2],     pl, vh);
                mma16816(o[4 * t2 + 2], ph, vh + 2);
                mma16816(o[4 * t2 + 2], pl, vh + 2);
                uint32_t bo2 = (uint32_t)((k0 + (lane & 15)) * KS
                                          + t2 * 32 + 8 + 16 * (lane >> 4)) * 2u;
                ldsm_x4t(vh, sb + VH_OFF + bo2);
                mma16816(o[4 * t2 + 1], ph, vh);
                mma16816(o[4 * t2 + 1], pl, vh);
                mma16816(o[4 * t2 + 3], ph, vh + 2);
                mma16816(o[4 * t2 + 3], pl, vh + 2);
            }
        }

        // ---- epilogue ----
        float* ob = out + (size_t)b * T * H;
#pragma unroll
        for (int nb = 0; nb < 8; nb++) {
            int c = nb * 8 + cb;
            *(float2*)&ob[r0 * H + c] = make_float2(o[nb][0] * inv0, o[nb][1] * inv0);
            *(float2*)&ob[r1 * H + c] = make_float2(o[nb][2] * inv1, o[nb][3] * inv1);
        }
    }
}

extern "C" void kernel_launch(void* const* d_in, const int* in_sizes, int n_in,
                              void* d_out, int out_size)
{
    const float* x  = (const float*)d_in[0];
    const float* Wk = (const float*)d_in[1];
    const float* Wq = (const float*)d_in[2];
    const float* Wv = (const float*)d_in[3];
    float* out = (float*)d_out;

    static bool attr_set = false;
    if (!attr_set) {
        cudaFuncSetAttribute(head_attn_v6,
                             cudaFuncAttributeMaxDynamicSharedMemorySize, SMEM_BYTES);
        attr_set = true;
    }
    convW_kernel<<<192, 256>>>(Wk, Wq, Wv);
    head_attn_v6<<<BATCH, NT, SMEM_BYTES>>>(x, out);
}

// round 10
// speedup vs baseline: 4.8145x; 1.0951x over previous
#include <cuda_runtime.h>
#include <cuda_fp16.h>
#include <cstdint>
#include <math.h>

#define BATCH 4096
#define T 96
#define C 256
#define H 64
#define SCALE 0.0625f
#define NT 256

// element strides (fp16)
#define XS 72
#define WS 72
#define KS 72
#define PS 104

// region A (phase 1), byte offsets
#define XH_OFF 0
#define WB_OFF 13824          // 3 W blocks (hi only), 9216 each
#define WBLK   9216           // region A ends 41472
// region B (kqv, overlays region A after phase 1)
#define KH_OFF 0
#define QH_OFF 13824
#define QL_OFF 27648
#define VH_OFF 41472          // ends 55296
// region C (P hi/lo, overlays k/q after S is in registers; v stays live)
#define PH_OFF 0
#define PL_OFF 19968          // ends 39936 < VH_OFF
#define SMEM_BYTES 55296

// -------- W pre-converted to fp16 (shared across all CTAs) --------
__device__ __half g_Wh[3][C * H];

__global__ void convW_kernel(const float* __restrict__ Wk,
                             const float* __restrict__ Wq,
                             const float* __restrict__ Wv)
{
    int idx = blockIdx.x * 256 + threadIdx.x;        // 0..49151
    int wm  = idx >> 14;
    int r   = idx & 16383;
    const float* W = (wm == 0) ? Wk : (wm == 1 ? Wq : Wv);
    g_Wh[wm][r] = __float2half_rn(W[r]);
}

__device__ __forceinline__ uint32_t smem_u32(const void* p) {
    uint32_t a;
    asm("{ .reg .u64 t; cvta.to.shared.u64 t, %1; cvt.u32.u64 %0, t; }" : "=r"(a) : "l"(p));
    return a;
}
__device__ __forceinline__ void ldsm_x4(unsigned* r, uint32_t addr) {
    asm volatile("ldmatrix.sync.aligned.m8n8.x4.shared.b16 {%0,%1,%2,%3}, [%4];"
                 : "=r"(r[0]), "=r"(r[1]), "=r"(r[2]), "=r"(r[3]) : "r"(addr));
}
__device__ __forceinline__ void ldsm_x4t(unsigned* r, uint32_t addr) {
    asm volatile("ldmatrix.sync.aligned.m8n8.x4.trans.shared.b16 {%0,%1,%2,%3}, [%4];"
                 : "=r"(r[0]), "=r"(r[1]), "=r"(r[2]), "=r"(r[3]) : "r"(addr));
}
__device__ __forceinline__ void mma16816(float* d, const unsigned* a, const unsigned* b) {
    asm volatile("mma.sync.aligned.m16n8k16.row.col.f32.f16.f16.f32 "
                 "{%0,%1,%2,%3}, {%4,%5,%6,%7}, {%8,%9}, {%0,%1,%2,%3};"
                 : "+f"(d[0]), "+f"(d[1]), "+f"(d[2]), "+f"(d[3])
                 : "r"(a[0]), "r"(a[1]), "r"(a[2]), "r"(a[3]), "r"(b[0]), "r"(b[1]));
}
__device__ __forceinline__ void split(float f, uint16_t& h, uint16_t& l) {
    __half hh = __float2half_rn(f);
    h = __half_as_ushort(hh);
    l = __half_as_ushort(__float2half_rn(f - __half2float(hh)));
}
__device__ __forceinline__ uint32_t pack2h(float a, float b) {
    return (uint32_t)__half_as_ushort(__float2half_rn(a))
         | ((uint32_t)__half_as_ushort(__float2half_rn(b)) << 16);
}

__global__ __launch_bounds__(NT, 2)
void head_attn_v7(const float* __restrict__ x,
                  float* __restrict__ out)
{
    extern __shared__ char smem[];
    const uint32_t sb = smem_u32(smem);
    const int tid  = threadIdx.x;
    const int w    = tid >> 5;
    const int lane = tid & 31;
    const int b    = blockIdx.x;

    // warp decomposition for phase 1: mh = w>>2 (m-half), q4 = w&3; 3 units each
    const int mh = w >> 2, q4 = w & 3;

    float acc[3][3][2][4];                 // [unit][mi][nb][4]
#pragma unroll
    for (int j = 0; j < 3; j++)
#pragma unroll
        for (int mi = 0; mi < 3; mi++)
#pragma unroll
            for (int nb = 0; nb < 2; nb++)
#pragma unroll
                for (int i = 0; i < 4; i++) acc[j][mi][nb][i] = 0.f;

    const float* xb = x + (size_t)b * T * C;

    // ---------------- phase 1: 4 K-chunks of 64, single-precision-pass on x ----------------
#pragma unroll 1
    for (int c = 0; c < 4; c++) {
        // stage x chunk [96][64] fp32 -> fp16 (hi only)
#pragma unroll
        for (int i = 0; i < 6; i++) {
            int idx = tid + i * NT;                  // 0..1535 float4
            int row = idx >> 4, c4 = idx & 15;
            float4 v = *(const float4*)&xb[row * C + c * 64 + c4 * 4];
            uint32_t off = (uint32_t)(row * XS + c4 * 4) * 2u;
            *(uint2*)(smem + XH_OFF + off) =
                make_uint2(pack2h(v.x, v.y), pack2h(v.z, v.w));
        }
        // stage W chunk [64][64] x3 (hi only), pure uint4 copies
#pragma unroll
        for (int i = 0; i < 6; i++) {
            int idx = tid + i * NT;                  // 0..1535 uint4
            int wm2 = idx >> 9;                      // 512 uint4 per matrix
            int r   = (idx >> 3) & 63;
            int c8  = idx & 7;
            uint4 v = *(const uint4*)(g_Wh[wm2] + (c * 64 + r) * H + c8 * 8);
            *(uint4*)(smem + WB_OFF + wm2 * WBLK + (uint32_t)(r * WS + c8 * 8) * 2u) = v;
        }
        __syncthreads();

        // mma over this chunk: xh * Wh (single pass)
#pragma unroll
        for (int kit = 0; kit < 4; kit++) {
            const int k0 = kit * 16;
            unsigned ah[3][4];
#pragma unroll
            for (int mi = 0; mi < 3; mi++) {
                uint32_t ao = (uint32_t)((mh * 48 + mi * 16 + (lane & 15)) * XS
                                         + k0 + 8 * (lane >> 4)) * 2u;
                ldsm_x4(ah[mi], sb + XH_OFF + ao);
            }
#pragma unroll
            for (int j = 0; j < 3; j++) {
                const int p  = q4 * 3 + j;
                const int wm = p >> 2, nq = p & 3;
                uint32_t bo = (uint32_t)((k0 + (lane & 15)) * WS
                                         + nq * 16 + 8 * (lane >> 4)) * 2u;
                unsigned bh[4];
                ldsm_x4t(bh, sb + WB_OFF + wm * WBLK + bo);
#pragma unroll
                for (int mi = 0; mi < 3; mi++)
#pragma unroll
                    for (int nb = 0; nb < 2; nb++)
                        mma16816(acc[j][mi][nb], ah[mi], bh + 2 * nb);
            }
        }
        __syncthreads();
    }

    // ---------------- spill: q hi/lo, k hi, v hi ----------------
#pragma unroll
    for (int j = 0; j < 3; j++) {
        const int p  = q4 * 3 + j;
        const int wm = p >> 2, nq = p & 3;
        char* hb = smem + (wm == 0 ? KH_OFF : (wm == 1 ? QH_OFF : VH_OFF));
#pragma unroll
        for (int mi = 0; mi < 3; mi++) {
            const int r0 = mh * 48 + mi * 16 + (lane >> 2);
#pragma unroll
            for (int nb = 0; nb < 2; nb++) {
                const int c0 = nq * 16 + nb * 8 + 2 * (lane & 3);
                if (wm == 1) {
                    char* lb = smem + QL_OFF;
                    uint16_t h0, l0, h1, l1;
                    split(acc[j][mi][nb][0], h0, l0); split(acc[j][mi][nb][1], h1, l1);
                    *(uint32_t*)(hb + (r0 * KS + c0) * 2) = (uint32_t)h0 | ((uint32_t)h1 << 16);
                    *(uint32_t*)(lb + (r0 * KS + c0) * 2) = (uint32_t)l0 | ((uint32_t)l1 << 16);
                    split(acc[j][mi][nb][2], h0, l0); split(acc[j][mi][nb][3], h1, l1);
                    *(uint32_t*)(hb + ((r0 + 8) * KS + c0) * 2) = (uint32_t)h0 | ((uint32_t)h1 << 16);
                    *(uint32_t*)(lb + ((r0 + 8) * KS + c0) * 2) = (uint32_t)l0 | ((uint32_t)l1 << 16);
                } else {
                    *(uint32_t*)(hb + (r0 * KS + c0) * 2) =
                        pack2h(acc[j][mi][nb][0], acc[j][mi][nb][1]);
                    *(uint32_t*)(hb + ((r0 + 8) * KS + c0) * 2) =
                        pack2h(acc[j][mi][nb][2], acc[j][mi][nb][3]);
                }
            }
        }
    }
    __syncthreads();

    // ---------------- phase 2: S = q k^T (warps 0..5, causal-trimmed) ----------------
    const int mt = w;
    float s[12][4];
    if (w < 6) {
#pragma unroll
        for (int nb = 0; nb < 12; nb++)
#pragma unroll
            for (int i = 0; i < 4; i++) s[nb][i] = 0.f;
#pragma unroll 1
        for (int kit = 0; kit < 4; kit++) {
            const int k0 = kit * 16;
            unsigned qh[4], ql[4];
            uint32_t ao = (uint32_t)((mt * 16 + (lane & 15)) * KS + k0 + 8 * (lane >> 4)) * 2u;
            ldsm_x4(qh, sb + QH_OFF + ao);
            ldsm_x4(ql, sb + QL_OFF + ao);
#pragma unroll 1
            for (int nb2 = 0; nb2 <= mt; nb2++) {    // causal: cols <= mt*16+15
                unsigned kh[4];
                uint32_t bo = (uint32_t)((nb2 * 16 + (lane & 7) + 8 * (lane >> 4)) * KS
                                         + k0 + 8 * ((lane >> 3) & 1)) * 2u;
                ldsm_x4(kh, sb + KH_OFF + bo);
                mma16816(s[2 * nb2],     qh, kh);
                mma16816(s[2 * nb2],     ql, kh);
                mma16816(s[2 * nb2 + 1], qh, kh + 2);
                mma16816(s[2 * nb2 + 1], ql, kh + 2);
            }
        }
    }
    __syncthreads();    // all warps: q,k reads done before P overlays them

    if (w < 6) {
        // ---- in-register causal softmax, P -> hi/lo fp16 (own 16 rows) ----
        const int r0 = mt * 16 + (lane >> 2);
        const int r1 = r0 + 8;
        const int cb = 2 * (lane & 3);
        float mx0 = -1e30f, mx1 = -1e30f;
#pragma unroll
        for (int nb = 0; nb < 12; nb++) {
            int c = nb * 8 + cb;
            if (c     <= r0) mx0 = fmaxf(mx0, s[nb][0]);
            if (c + 1 <= r0) mx0 = fmaxf(mx0, s[nb][1]);
            if (c     <= r1) mx1 = fmaxf(mx1, s[nb][2]);
            if (c + 1 <= r1) mx1 = fmaxf(mx1, s[nb][3]);
        }
        mx0 = fmaxf(mx0, __shfl_xor_sync(0xffffffffu, mx0, 1));
        mx0 = fmaxf(mx0, __shfl_xor_sync(0xffffffffu, mx0, 2));
        mx1 = fmaxf(mx1, __shfl_xor_sync(0xffffffffu, mx1, 1));
        mx1 = fmaxf(mx1, __shfl_xor_sync(0xffffffffu, mx1, 2));
        mx0 *= SCALE; mx1 *= SCALE;

        float sum0 = 0.f, sum1 = 0.f;
        uint16_t* PH = (uint16_t*)(smem + PH_OFF);
        uint16_t* PL = (uint16_t*)(smem + PL_OFF);
#pragma unroll
        for (int nb = 0; nb < 12; nb++) {
            int c = nb * 8 + cb;
            float p0 = (c     <= r0) ? __expf(s[nb][0] * SCALE - mx0) : 0.f;
            float p1 = (c + 1 <= r0) ? __expf(s[nb][1] * SCALE - mx0) : 0.f;
            float p2 = (c     <= r1) ? __expf(s[nb][2] * SCALE - mx1) : 0.f;
            float p3 = (c + 1 <= r1) ? __expf(s[nb][3] * SCALE - mx1) : 0.f;
            sum0 += p0 + p1; sum1 += p2 + p3;
            uint16_t h0, l0, h1, l1;
            split(p0, h0, l0); split(p1, h1, l1);
            *(uint32_t*)&PH[r0 * PS + c] = (uint32_t)h0 | ((uint32_t)h1 << 16);
            *(uint32_t*)&PL[r0 * PS + c] = (uint32_t)l0 | ((uint32_t)l1 << 16);
            split(p2, h0, l0); split(p3, h1, l1);
            *(uint32_t*)&PH[r1 * PS + c] = (uint32_t)h0 | ((uint32_t)h1 << 16);
            *(uint32_t*)&PL[r1 * PS + c] = (uint32_t)l0 | ((uint32_t)l1 << 16);
        }
        sum0 += __shfl_xor_sync(0xffffffffu, sum0, 1);
        sum0 += __shfl_xor_sync(0xffffffffu, sum0, 2);
        sum1 += __shfl_xor_sync(0xffffffffu, sum1, 1);
        sum1 += __shfl_xor_sync(0xffffffffu, sum1, 2);
        const float inv0 = 1.f / sum0;
        const float inv1 = 1.f / sum1;
        __syncwarp();

        // ---- phase 3: O = P @ v, causal-trimmed k-loop (kit <= mt) ----
        float o[8][4];
#pragma unroll
        for (int nb = 0; nb < 8; nb++)
#pragma unroll
            for (int i = 0; i < 4; i++) o[nb][i] = 0.f;
#pragma unroll 1
        for (int kit = 0; kit <= mt; kit++) {
            const int k0 = kit * 16;
            unsigned ph[4], pl[4];
            uint32_t ao = (uint32_t)((mt * 16 + (lane & 15)) * PS + k0 + 8 * (lane >> 4)) * 2u;
            ldsm_x4(ph, sb + PH_OFF + ao);
            ldsm_x4(pl, sb + PL_OFF + ao);
#pragma unroll
            for (int t2 = 0; t2 < 2; t2++) {
                unsigned vh[4];
                uint32_t bo = (uint32_t)((k0 + (lane & 15)) * KS
                                         + t2 * 32 + 16 * (lane >> 4)) * 2u;
                ldsm_x4t(vh, sb + VH_OFF + bo);
                mma16816(o[4 * t2],     ph, vh);
                mma16816(o[4 * t2],     pl, vh);
                mma16816(o[4 * t2 + 2], ph, vh + 2);
                mma16816(o[4 * t2 + 2], pl, vh + 2);
                uint32_t bo2 = (uint32_t)((k0 + (lane & 15)) * KS
                                          + t2 * 32 + 8 + 16 * (lane >> 4)) * 2u;
                ldsm_x4t(vh, sb + VH_OFF + bo2);
                mma16816(o[4 * t2 + 1], ph, vh);
                mma16816(o[4 * t2 + 1], pl, vh);
                mma16816(o[4 * t2 + 3], ph, vh + 2);
                mma16816(o[4 * t2 + 3], pl, vh + 2);
            }
        }

        // ---- epilogue ----
        float* ob = out + (size_t)b * T * H;
#pragma unroll
        for (int nb = 0; nb < 8; nb++) {
            int c = nb * 8 + cb;
            *(float2*)&ob[r0 * H + c] = make_float2(o[nb][0] * inv0, o[nb][1] * inv0);
            *(float2*)&ob[r1 * H + c] = make_float2(o[nb][2] * inv1, o[nb][3] * inv1);
        }
    }
}

extern "C" void kernel_launch(void* const* d_in, const int* in_sizes, int n_in,
                              void* d_out, int out_size)
{
    const float* x  = (const float*)d_in[0];
    const float* Wk = (const float*)d_in[1];
    const float* Wq = (const float*)d_in[2];
    const float* Wv = (const float*)d_in[3];
    float* out = (float*)d_out;

    static bool attr_set = false;
    if (!attr_set) {
        cudaFuncSetAttribute(head_attn_v7,
                             cudaFuncAttributeMaxDynamicSharedMemorySize, SMEM_BYTES);
        attr_set = true;
    }
    convW_kernel<<<192, 256>>>(Wk, Wq, Wv);
    head_attn_v7<<<BATCH, NT, SMEM_BYTES>>>(x, out);
}

// round 11
// speedup vs baseline: 6.6145x; 1.3739x over previous
#include <cuda_runtime.h>
#include <cuda_fp16.h>
#include <cstdint>
#include <math.h>

#define BATCH 4096
#define T 96
#define C 256
#define H 64
#define SCALE 0.0625f
#define NT 256

// element strides (fp16)
#define XS 72
#define WS 72
#define KS 72
#define PS 104
#define X32S 68     // fp32 staging stride (floats)

// region A (phase 1), byte offsets
#define XH_OFF 0              // 13824
#define WB_OFF 13824          // 3 W blocks (hi only), 9216 each -> ends 41472
#define WBLK   9216
#define X32_OFF 41472         // 2 bufs x 96*68*4 = 2*26112 -> ends 93696
#define X32B   26112
// region B (kqv, overlays region A after phase 1)
#define KH_OFF 0
#define QH_OFF 13824
#define QL_OFF 27648
#define VH_OFF 41472          // ends 55296 (X32 dead by then)
// region C (P hi/lo, overlays k/q after S consumed; v stays live)
#define PH_OFF 0
#define PL_OFF 19968          // ends 39936
// softmax scratch (above VH end, below X32 end — X32 dead)
#define SMAX_OFF 55296        // [96][9] floats = 3456
#define RMAX_OFF 58752        // [96] floats
#define INV_OFF  59136        // [96] floats
#define SMEM_BYTES 93696

// -------- W pre-converted to fp16 (shared across all CTAs) --------
__device__ __half g_Wh[3][C * H];

__global__ void convW_kernel(const float* __restrict__ Wk,
                             const float* __restrict__ Wq,
                             const float* __restrict__ Wv)
{
    int idx = blockIdx.x * 256 + threadIdx.x;        // 0..49151
    int wm  = idx >> 14;
    int r   = idx & 16383;
    const float* W = (wm == 0) ? Wk : (wm == 1 ? Wq : Wv);
    g_Wh[wm][r] = __float2half_rn(W[r]);
}

__device__ __forceinline__ uint32_t smem_u32(const void* p) {
    uint32_t a;
    asm("{ .reg .u64 t; cvta.to.shared.u64 t, %1; cvt.u32.u64 %0, t; }" : "=r"(a) : "l"(p));
    return a;
}
__device__ __forceinline__ void ldsm_x4(unsigned* r, uint32_t addr) {
    asm volatile("ldmatrix.sync.aligned.m8n8.x4.shared.b16 {%0,%1,%2,%3}, [%4];"
                 : "=r"(r[0]), "=r"(r[1]), "=r"(r[2]), "=r"(r[3]) : "r"(addr));
}
__device__ __forceinline__ void ldsm_x4t(unsigned* r, uint32_t addr) {
    asm volatile("ldmatrix.sync.aligned.m8n8.x4.trans.shared.b16 {%0,%1,%2,%3}, [%4];"
                 : "=r"(r[0]), "=r"(r[1]), "=r"(r[2]), "=r"(r[3]) : "r"(addr));
}
__device__ __forceinline__ void mma16816(float* d, const unsigned* a, const unsigned* b) {
    asm volatile("mma.sync.aligned.m16n8k16.row.col.f32.f16.f16.f32 "
                 "{%0,%1,%2,%3}, {%4,%5,%6,%7}, {%8,%9}, {%0,%1,%2,%3};"
                 : "+f"(d[0]), "+f"(d[1]), "+f"(d[2]), "+f"(d[3])
                 : "r"(a[0]), "r"(a[1]), "r"(a[2]), "r"(a[3]), "r"(b[0]), "r"(b[1]));
}
__device__ __forceinline__ void split(float f, uint16_t& h, uint16_t& l) {
    __half hh = __float2half_rn(f);
    h = __half_as_ushort(hh);
    l = __half_as_ushort(__float2half_rn(f - __half2float(hh)));
}
__device__ __forceinline__ uint32_t pack2h(float a, float b) {
    return (uint32_t)__half_as_ushort(__float2half_rn(a))
         | ((uint32_t)__half_as_ushort(__float2half_rn(b)) << 16);
}
__device__ __forceinline__ void cp16(uint32_t dst, const void* src) {
    asm volatile("cp.async.cg.shared.global [%0], [%1], 16;"
                 :: "r"(dst), "l"(__cvta_generic_to_global(src)) : "memory");
}
#define CP_COMMIT() asm volatile("cp.async.commit_group;" ::: "memory")
#define CP_WAIT0()  asm volatile("cp.async.wait_group 0;" ::: "memory")

__global__ __launch_bounds__(NT, 2)
void head_attn_v8(const float* __restrict__ x,
                  float* __restrict__ out)
{
    extern __shared__ char smem[];
    const uint32_t sb = smem_u32(smem);
    const int tid  = threadIdx.x;
    const int w    = tid >> 5;
    const int lane = tid & 31;
    const int b    = blockIdx.x;
    const float* xb = x + (size_t)b * T * C;

    const int srow = tid >> 4, sc4 = tid & 15;       // x staging coords (16 thr/row)
    const int wwm = tid >> 9, wr0 = (tid >> 3) & 63, wc8 = tid & 7; // unused base; W below

    // ---- cp.async issue helpers (each thread: 6 x-16B, 6 w-16B) ----
    // x chunk ck -> buf bf
#define CP_X(ck, bf) do {                                                          \
    _Pragma("unroll")                                                              \
    for (int i = 0; i < 6; i++) {                                                  \
        int idx = tid + i * NT;                                                    \
        int row = idx >> 4, c4 = idx & 15;                                         \
        cp16(sb + X32_OFF + (bf) * X32B + (uint32_t)(row * X32S + c4 * 4) * 4u,    \
             xb + row * C + (ck) * 64 + c4 * 4);                                   \
    }                                                                              \
} while (0)
#define CP_W(ck) do {                                                              \
    _Pragma("unroll")                                                              \
    for (int i = 0; i < 6; i++) {                                                  \
        int idx = tid + i * NT;                                                    \
        int wm2 = idx >> 9, r = (idx >> 3) & 63, c8 = idx & 7;                     \
        cp16(sb + WB_OFF + wm2 * WBLK + (uint32_t)(r * WS + c8 * 8) * 2u,          \
             g_Wh[wm2] + ((ck) * 64 + r) * H + c8 * 8);                            \
    }                                                                              \
} while (0)

    // prologue: x0, x1, W0 in flight
    CP_X(0, 0); CP_COMMIT();
    CP_X(1, 1); CP_COMMIT();
    CP_W(0);    CP_COMMIT();

    const int mh = w >> 2, q4 = w & 3;
    float acc[3][3][2][4];
#pragma unroll
    for (int j = 0; j < 3; j++)
#pragma unroll
        for (int mi = 0; mi < 3; mi++)
#pragma unroll
            for (int nb = 0; nb < 2; nb++)
#pragma unroll
                for (int i = 0; i < 4; i++) acc[j][mi][nb][i] = 0.f;

    CP_WAIT0();
    __syncthreads();

    // ---------------- phase 1: 4 pipelined K-chunks of 64 ----------------
#pragma unroll 1
    for (int c = 0; c < 4; c++) {
        // convert fp32 staging -> fp16 XH
#pragma unroll
        for (int i = 0; i < 6; i++) {
            int idx = tid + i * NT;
            int row = idx >> 4, c4 = idx & 15;
            const float4 v = *(const float4*)(smem + X32_OFF + (c & 1) * X32B
                                              + (uint32_t)(row * X32S + c4 * 4) * 4u);
            *(uint2*)(smem + XH_OFF + (uint32_t)(row * XS + c4 * 4) * 2u) =
                make_uint2(pack2h(v.x, v.y), pack2h(v.z, v.w));
        }
        CP_WAIT0();            // W_c complete (and any pending x)
        __syncthreads();       // XH/WH visible; X32 buf reads done
        if (c < 2) { CP_X(c + 2, c & 1); CP_COMMIT(); }

        // mma over this chunk: xh * Wh
#pragma unroll
        for (int kit = 0; kit < 4; kit++) {
            const int k0 = kit * 16;
            unsigned ah[3][4];
#pragma unroll
            for (int mi = 0; mi < 3; mi++) {
                uint32_t ao = (uint32_t)((mh * 48 + mi * 16 + (lane & 15)) * XS
                                         + k0 + 8 * (lane >> 4)) * 2u;
                ldsm_x4(ah[mi], sb + XH_OFF + ao);
            }
#pragma unroll
            for (int j = 0; j < 3; j++) {
                const int p  = q4 * 3 + j;
                const int wm = p >> 2, nq = p & 3;
                uint32_t bo = (uint32_t)((k0 + (lane & 15)) * WS
                                         + nq * 16 + 8 * (lane >> 4)) * 2u;
                unsigned bh[4];
                ldsm_x4t(bh, sb + WB_OFF + wm * WBLK + bo);
#pragma unroll
                for (int mi = 0; mi < 3; mi++)
#pragma unroll
                    for (int nb = 0; nb < 2; nb++)
                        mma16816(acc[j][mi][nb], ah[mi], bh + 2 * nb);
            }
        }
        __syncthreads();       // XH/WH free
        if (c < 3) { CP_W(c + 1); CP_COMMIT(); }
    }

    // ---------------- spill: q hi/lo, k hi, v hi ----------------
#pragma unroll
    for (int j = 0; j < 3; j++) {
        const int p  = q4 * 3 + j;
        const int wm = p >> 2, nq = p & 3;
        char* hb = smem + (wm == 0 ? KH_OFF : (wm == 1 ? QH_OFF : VH_OFF));
#pragma unroll
        for (int mi = 0; mi < 3; mi++) {
            const int r0 = mh * 48 + mi * 16 + (lane >> 2);
#pragma unroll
            for (int nb = 0; nb < 2; nb++) {
                const int c0 = nq * 16 + nb * 8 + 2 * (lane & 3);
                if (wm == 1) {
                    char* lb = smem + QL_OFF;
                    uint16_t h0, l0, h1, l1;
                    split(acc[j][mi][nb][0], h0, l0); split(acc[j][mi][nb][1], h1, l1);
                    *(uint32_t*)(hb + (r0 * KS + c0) * 2) = (uint32_t)h0 | ((uint32_t)h1 << 16);
                    *(uint32_t*)(lb + (r0 * KS + c0) * 2) = (uint32_t)l0 | ((uint32_t)l1 << 16);
                    split(acc[j][mi][nb][2], h0, l0); split(acc[j][mi][nb][3], h1, l1);
                    *(uint32_t*)(hb + ((r0 + 8) * KS + c0) * 2) = (uint32_t)h0 | ((uint32_t)h1 << 16);
                    *(uint32_t*)(lb + ((r0 + 8) * KS + c0) * 2) = (uint32_t)l0 | ((uint32_t)l1 << 16);
                } else {
                    *(uint32_t*)(hb + (r0 * KS + c0) * 2) =
                        pack2h(acc[j][mi][nb][0], acc[j][mi][nb][1]);
                    *(uint32_t*)(hb + ((r0 + 8) * KS + c0) * 2) =
                        pack2h(acc[j][mi][nb][2], acc[j][mi][nb][3]);
                }
            }
        }
    }
    __syncthreads();

    // ---------------- phase 2: S = q k^T, balanced units across 8 warps ----------------
    // unit encoding: mt*8+nb2 (6 bits), three slots per warp
    const uint64_t U0 = 0x28ULL | (0x2BULL << 6) | (0x20ULL << 12) | (0x23ULL << 18)
                      | (0x18ULL << 24) | (0x10ULL << 30) | (0x08ULL << 36);
    const uint64_t U1 = 0x29ULL | (0x2CULL << 6) | (0x21ULL << 12) | (0x24ULL << 18)
                      | (0x19ULL << 24) | (0x11ULL << 30) | (0x09ULL << 36);
    const uint64_t U2 = 0x2AULL | (0x2DULL << 6) | (0x22ULL << 12) | (0x1BULL << 18)
                      | (0x1AULL << 24) | (0x12ULL << 30);
    const uint32_t CNT2 = 0x12333333u;
    const int n2 = (CNT2 >> (4 * w)) & 15;
    const int u0 = (int)((U0 >> (6 * w)) & 63);
    const int u1 = (int)((U1 >> (6 * w)) & 63);
    const int u2 = (int)((U2 >> (6 * w)) & 63);

    float s[3][2][4];
#pragma unroll
    for (int u = 0; u < 3; u++)
#pragma unroll
        for (int nb = 0; nb < 2; nb++)
#pragma unroll
            for (int i = 0; i < 4; i++) s[u][nb][i] = 0.f;

#pragma unroll
    for (int u = 0; u < 3; u++) {
        if (u >= n2) break;
        const int unit = (u == 0) ? u0 : ((u == 1) ? u1 : u2);
        const int mt = unit >> 3, nb2 = unit & 7;
#pragma unroll
        for (int kit = 0; kit < 4; kit++) {
            const int k0 = kit * 16;
            unsigned qh[4], ql[4], kh[4];
            uint32_t ao = (uint32_t)((mt * 16 + (lane & 15)) * KS + k0 + 8 * (lane >> 4)) * 2u;
            ldsm_x4(qh, sb + QH_OFF + ao);
            ldsm_x4(ql, sb + QL_OFF + ao);
            uint32_t bo = (uint32_t)((nb2 * 16 + (lane & 7) + 8 * (lane >> 4)) * KS
                                     + k0 + 8 * ((lane >> 3) & 1)) * 2u;
            ldsm_x4(kh, sb + KH_OFF + bo);
            mma16816(s[u][0], qh, kh);
            mma16816(s[u][0], ql, kh);
            mma16816(s[u][1], qh, kh + 2);
            mma16816(s[u][1], ql, kh + 2);
        }
    }

    // partial row-max per unit -> SMAX[r][nb2]
    {
        float* SMX = (float*)(smem + SMAX_OFF);
#pragma unroll
        for (int u = 0; u < 3; u++) {
            if (u >= n2) break;
            const int unit = (u == 0) ? u0 : ((u == 1) ? u1 : u2);
            const int mt = unit >> 3, nb2 = unit & 7;
            const int r0 = mt * 16 + (lane >> 2), r1 = r0 + 8;
            const int cbase = nb2 * 16 + 2 * (lane & 3);
            const bool diag = (nb2 == mt);
            float m0 = -1e30f, m1 = -1e30f;
#pragma unroll
            for (int nb = 0; nb < 2; nb++) {
                int c = cbase + nb * 8;
                if (!diag || c     <= r0) m0 = fmaxf(m0, s[u][nb][0]);
                if (!diag || c + 1 <= r0) m0 = fmaxf(m0, s[u][nb][1]);
                if (!diag || c     <= r1) m1 = fmaxf(m1, s[u][nb][2]);
                if (!diag || c + 1 <= r1) m1 = fmaxf(m1, s[u][nb][3]);
            }
            m0 = fmaxf(m0, __shfl_xor_sync(0xffffffffu, m0, 1));
            m0 = fmaxf(m0, __shfl_xor_sync(0xffffffffu, m0, 2));
            m1 = fmaxf(m1, __shfl_xor_sync(0xffffffffu, m1, 1));
            m1 = fmaxf(m1, __shfl_xor_sync(0xffffffffu, m1, 2));
            if ((lane & 3) == 0) {
                SMX[r0 * 9 + nb2] = m0;
                SMX[r1 * 9 + nb2] = m1;
            }
        }
    }
    __syncthreads();

    // row-max combine
    if (tid < T) {
        const float* SMX = (const float*)(smem + SMAX_OFF);
        float m = SMX[tid * 9];
        const int segs = tid >> 4;
#pragma unroll 1
        for (int sg = 1; sg <= segs; sg++) m = fmaxf(m, SMX[tid * 9 + sg]);
        ((float*)(smem + RMAX_OFF))[tid] = m;
    }
    __syncthreads();

    // exp + P write (unnormalized) + partial sums
    {
        const float* RMX = (const float*)(smem + RMAX_OFF);
        float* SMX = (float*)(smem + SMAX_OFF);
        uint16_t* PH = (uint16_t*)(smem + PH_OFF);
        uint16_t* PL = (uint16_t*)(smem + PL_OFF);
#pragma unroll
        for (int u = 0; u < 3; u++) {
            if (u >= n2) break;
            const int unit = (u == 0) ? u0 : ((u == 1) ? u1 : u2);
            const int mt = unit >> 3, nb2 = unit & 7;
            const int r0 = mt * 16 + (lane >> 2), r1 = r0 + 8;
            const int cbase = nb2 * 16 + 2 * (lane & 3);
            const bool diag = (nb2 == mt);
            const float rm0 = RMX[r0] * SCALE, rm1 = RMX[r1] * SCALE;
            float sum0 = 0.f, sum1 = 0.f;
#pragma unroll
            for (int nb = 0; nb < 2; nb++) {
                int c = cbase + nb * 8;
                float p0 = (!diag || c     <= r0) ? __expf(s[u][nb][0] * SCALE - rm0) : 0.f;
                float p1 = (!diag || c + 1 <= r0) ? __expf(s[u][nb][1] * SCALE - rm0) : 0.f;
                float p2 = (!diag || c     <= r1) ? __expf(s[u][nb][2] * SCALE - rm1) : 0.f;
                float p3 = (!diag || c + 1 <= r1) ? __expf(s[u][nb][3] * SCALE - rm1) : 0.f;
                sum0 += p0 + p1; sum1 += p2 + p3;
                uint16_t h0, l0, h1, l1;
                split(p0, h0, l0); split(p1, h1, l1);
                *(uint32_t*)&PH[r0 * PS + c] = (uint32_t)h0 | ((uint32_t)h1 << 16);
                *(uint32_t*)&PL[r0 * PS + c] = (uint32_t)l0 | ((uint32_t)l1 << 16);
                split(p2, h0, l0); split(p3, h1, l1);
                *(uint32_t*)&PH[r1 * PS + c] = (uint32_t)h0 | ((uint32_t)h1 << 16);
                *(uint32_t*)&PL[r1 * PS + c] = (uint32_t)l0 | ((uint32_t)l1 << 16);
            }
            sum0 += __shfl_xor_sync(0xffffffffu, sum0, 1);
            sum0 += __shfl_xor_sync(0xffffffffu, sum0, 2);
            sum1 += __shfl_xor_sync(0xffffffffu, sum1, 1);
            sum1 += __shfl_xor_sync(0xffffffffu, sum1, 2);
            if ((lane & 3) == 0) {
                SMX[r0 * 9 + nb2] = sum0;
                SMX[r1 * 9 + nb2] = sum1;
            }
        }
    }
    __syncthreads();

    // row-sum combine -> inv
    if (tid < T) {
        const float* SMX = (const float*)(smem + SMAX_OFF);
        float sm = SMX[tid * 9];
        const int segs = tid >> 4;
#pragma unroll 1
        for (int sg = 1; sg <= segs; sg++) sm += SMX[tid * 9 + sg];
        ((float*)(smem + INV_OFF))[tid] = 1.f / sm;
    }
    __syncthreads();

    // ---------------- phase 3: O = P @ v, balanced (mt, nh) units ----------------
    const uint32_t V0 = 0x547698BAu, V1 = 0x10320000u, CNT3 = 0x22221111u;
    const int n3  = (CNT3 >> (4 * w)) & 15;
    const int vu0 = (V0 >> (4 * w)) & 15;
    const int vu1 = (V1 >> (4 * w)) & 15;
    const float* INV = (const float*)(smem + INV_OFF);
    float* ob = out + (size_t)b * T * H;

    float o[2][4][4];
#pragma unroll
    for (int u = 0; u < 2; u++)
#pragma unroll
        for (int nb = 0; nb < 4; nb++)
#pragma unroll
            for (int i = 0; i < 4; i++) o[u][nb][i] = 0.f;

#pragma unroll
    for (int u = 0; u < 2; u++) {
        if (u >= n3) break;
        const int unit = (u == 0) ? vu0 : vu1;
        const int mt = unit >> 1, nh = unit & 1;
#pragma unroll 1
        for (int kit = 0; kit <= mt; kit++) {
            const int k0 = kit * 16;
            unsigned ph[4], pl[4], vh[4];
            uint32_t ao = (uint32_t)((mt * 16 + (lane & 15)) * PS + k0 + 8 * (lane >> 4)) * 2u;
            ldsm_x4(ph, sb + PH_OFF + ao);
            ldsm_x4(pl, sb + PL_OFF + ao);
            uint32_t bo = (uint32_t)((k0 + (lane & 15)) * KS + nh * 32 + 16 * (lane >> 4)) * 2u;
            ldsm_x4t(vh, sb + VH_OFF + bo);
            mma16816(o[u][0], ph, vh);
            mma16816(o[u][0], pl, vh);
            mma16816(o[u][2], ph, vh + 2);
            mma16816(o[u][2], pl, vh + 2);
            uint32_t bo2 = bo + 16u;   // +8 cols
            ldsm_x4t(vh, sb + VH_OFF + bo2);
            mma16816(o[u][1], ph, vh);
            mma16816(o[u][1], pl, vh);
            mma16816(o[u][3], ph, vh + 2);
            mma16816(o[u][3], pl, vh + 2);
        }
        // epilogue for this unit
        const int r0 = mt * 16 + (lane >> 2), r1 = r0 + 8;
        const float inv0 = INV[r0], inv1 = INV[r1];
#pragma unroll
        for (int nb = 0; nb < 4; nb++) {
            int c = nh * 32 + nb * 8 + 2 * (lane & 3);
            *(float2*)&ob[r0 * H + c] = make_float2(o[u][nb][0] * inv0, o[u][nb][1] * inv0);
            *(float2*)&ob[r1 * H + c] = make_float2(o[u][nb][2] * inv1, o[u][nb][3] * inv1);
        }
    }
}

extern "C" void kernel_launch(void* const* d_in, const int* in_sizes, int n_in,
                              void* d_out, int out_size)
{
    const float* x  = (const float*)d_in[0];
    const float* Wk = (const float*)d_in[1];
    const float* Wq = (const float*)d_in[2];
    const float* Wv = (const float*)d_in[3];
    float* out = (float*)d_out;

    static bool attr_set = false;
    if (!attr_set) {
        cudaFuncSetAttribute(head_attn_v8,
                             cudaFuncAttributeMaxDynamicSharedMemorySize, SMEM_BYTES);
        attr_set = true;
    }
    convW_kernel<<<192, 256>>>(Wk, Wq, Wv);
    head_attn_v8<<<BATCH, NT, SMEM_BYTES>>>(x, out);
}